// round 7
// baseline (speedup 1.0000x reference)
#include <cuda_runtime.h>
#include <cuda_bf16.h>
#include <stdint.h>
#include <math.h>

#define S  4096
#define D  2048
#define FF 8192
#define EPSF 1.1920929e-07f

#define KC 32                    // bf16 k per chunk
// CTA tile 256x128, warp tile 64x64, 8 warps (4x2), 1 CTA/SM
#define A_OP 20480               // 256 rows x 80B
#define B_OP 10240               // 128 rows x 80B
#define STGB (2 * A_OP + 2 * B_OP)   // Ah, Al, Bh, Bl = 61440
#define NSTAGE 3
#define SMEMB (NSTAGE * STGB)    // 184320

// ------------------------- device scratch (no allocs allowed) ---------------
__device__ __nv_bfloat16 g_wq_h[(size_t)D*D],  g_wq_l[(size_t)D*D];
__device__ __nv_bfloat16 g_wk_h[(size_t)D*D],  g_wk_l[(size_t)D*D];
__device__ __nv_bfloat16 g_wv_h[(size_t)D*D],  g_wv_l[(size_t)D*D];
__device__ __nv_bfloat16 g_wo_h[(size_t)D*D],  g_wo_l[(size_t)D*D];
__device__ __nv_bfloat16 g_wg_h[(size_t)FF*D], g_wg_l[(size_t)FF*D];
__device__ __nv_bfloat16 g_wu_h[(size_t)FF*D], g_wu_l[(size_t)FF*D];
__device__ __nv_bfloat16 g_wd_h[(size_t)D*FF], g_wd_l[(size_t)D*FF];
__device__ __nv_bfloat16 g_h_h[(size_t)S*D],   g_h_l[(size_t)S*D];
__device__ __nv_bfloat16 g_q_h[(size_t)S*D],   g_q_l[(size_t)S*D];
__device__ __nv_bfloat16 g_k_h[(size_t)S*D],   g_k_l[(size_t)S*D];
__device__ __nv_bfloat16 g_vt_h[(size_t)D*S],  g_vt_l[(size_t)D*S];
__device__ __nv_bfloat16 g_p_h[(size_t)S*S],   g_p_l[(size_t)S*S];
__device__ __nv_bfloat16 g_av_h[(size_t)S*D],  g_av_l[(size_t)S*D];
__device__ __nv_bfloat16 g_h2_h[(size_t)S*D],  g_h2_l[(size_t)S*D];
__device__ __nv_bfloat16 g_act_h[(size_t)S*FF],g_act_l[(size_t)S*FF];
__device__ float g_qf[(size_t)S*D];
__device__ float g_kf[(size_t)S*D];
__device__ float g_vf[(size_t)S*D];
__device__ float g_sc[(size_t)S*S];
__device__ float g_avf[(size_t)S*D];
__device__ float g_x1[(size_t)S*D];
__device__ float g_gf[(size_t)S*FF];
__device__ float g_uf[(size_t)S*FF];

// ------------------------- helpers ------------------------------------------
__device__ __forceinline__ uint32_t smem_u32(const void* p) {
    uint32_t a;
    asm("{ .reg .u64 t; cvta.to.shared.u64 t, %1; cvt.u32.u64 %0, t; }"
        : "=r"(a) : "l"(p));
    return a;
}

__device__ __forceinline__ void cpasync16(uint32_t dst, const void* src) {
    asm volatile("cp.async.cg.shared.global [%0], [%1], 16;"
                 :: "r"(dst), "l"(src) : "memory");
}

__device__ __forceinline__ void ldsm4(uint32_t addr, uint32_t& r0, uint32_t& r1,
                                      uint32_t& r2, uint32_t& r3) {
    asm volatile("ldmatrix.sync.aligned.m8n8.x4.shared.b16 {%0,%1,%2,%3}, [%4];"
                 : "=r"(r0), "=r"(r1), "=r"(r2), "=r"(r3) : "r"(addr));
}

__device__ __forceinline__ void mma16816(float* c, const uint32_t* a, const uint32_t* b) {
    asm volatile("mma.sync.aligned.m16n8k16.row.col.f32.bf16.bf16.f32 "
                 "{%0,%1,%2,%3}, {%4,%5,%6,%7}, {%8,%9}, {%0,%1,%2,%3};"
                 : "+f"(c[0]), "+f"(c[1]), "+f"(c[2]), "+f"(c[3])
                 : "r"(a[0]), "r"(a[1]), "r"(a[2]), "r"(a[3]),
                   "r"(b[0]), "r"(b[1]));
}

// ------------------------- tensor-core split GEMM ----------------------------
// C[M,N] = alpha * (Ahi+Alo)[M,K] @ (Bhi+Blo)[N,K]^T (+res). bf16 3-pass split.
// CTA tile 256x128, warp tile 64x64, 3-stage cp.async pipeline.
__global__ __launch_bounds__(256, 1)
void gemm_mma(const __nv_bfloat16* __restrict__ Ah, const __nv_bfloat16* __restrict__ Al,
              const __nv_bfloat16* __restrict__ Bh, const __nv_bfloat16* __restrict__ Bl,
              float* __restrict__ C, const float* __restrict__ res,
              int M, int N, int K, float alpha)
{
    extern __shared__ __align__(128) char smem[];
    const int tid = threadIdx.x;
    const int wid = tid >> 5, lane = tid & 31;
    const int warp_m = wid & 3, warp_n = wid >> 2;       // 4 x 2
    const int bm = blockIdx.y * 256, bn = blockIdx.x * 128;
    const uint32_t sb = smem_u32(smem);
    const int nch = K / KC;

    float acc[4][8][4];
#pragma unroll
    for (int mt = 0; mt < 4; mt++)
#pragma unroll
        for (int nt = 0; nt < 8; nt++)
#pragma unroll
            for (int e = 0; e < 4; e++) acc[mt][nt][e] = 0.f;

    const int lrow = tid >> 2;   // 0..63
    const int lc   = tid & 3;    // 16B chunk within 64B row

    // ---- stage loader: 12 cp.async per thread ------------------------------
    auto issue = [&](int stage, int chunk) {
        const int k0 = chunk * KC;
        const uint32_t base = sb + stage * STGB;
        // A: 256 rows hi/lo
#pragma unroll
        for (int r = 0; r < 4; r++) {
            const int ar = lrow + 64 * r;
            const uint32_t d = base + ar * 80 + lc * 16;
            const size_t g = (size_t)(bm + ar) * K + k0 + lc * 8;
            cpasync16(d,        Ah + g);
            cpasync16(d + A_OP, Al + g);
        }
        // B: 128 rows hi/lo
#pragma unroll
        for (int r = 0; r < 2; r++) {
            const int br = lrow + 64 * r;
            const uint32_t d = base + 2 * A_OP + br * 80 + lc * 16;
            const size_t g = (size_t)(bn + br) * K + k0 + lc * 8;
            cpasync16(d,        Bh + g);
            cpasync16(d + B_OP, Bl + g);
        }
    };

    // prologue: 2 stages in flight
    issue(0, 0);
    asm volatile("cp.async.commit_group;" ::: "memory");
    issue(1, 1);
    asm volatile("cp.async.commit_group;" ::: "memory");

    // ldmatrix lane addressing
    const int quad = lane >> 3, l8 = lane & 7;
    const int a_r = (quad & 1) * 8 + l8;
    const int a_c = (quad >> 1) * 8;
    const int b_r = (quad >> 1) * 8 + l8;
    const int b_c = (quad & 1) * 8;

    int stage = 0;
    for (int i = 0; i < nch; i++) {
        asm volatile("cp.async.wait_group 1;" ::: "memory");
        __syncthreads();
        if (i + 2 < nch) {
            int ns = stage + 2; if (ns >= NSTAGE) ns -= NSTAGE;
            issue(ns, i + 2);
        }
        asm volatile("cp.async.commit_group;" ::: "memory");

        const uint32_t st = sb + stage * STGB;
#pragma unroll
        for (int ks = 0; ks < 2; ks++) {
            const int ko = ks * 16;
            uint32_t ah[4][4], al[4][4], b[8][2];
#pragma unroll
            for (int mt = 0; mt < 4; mt++) {
                const uint32_t ad = st + (warp_m * 64 + mt * 16 + a_r) * 80 + (a_c + ko) * 2;
                ldsm4(ad,        ah[mt][0], ah[mt][1], ah[mt][2], ah[mt][3]);
                ldsm4(ad + A_OP, al[mt][0], al[mt][1], al[mt][2], al[mt][3]);
            }
#pragma unroll
            for (int p = 0; p < 4; p++) {
                const uint32_t bd = st + 2 * A_OP +
                                    (warp_n * 64 + p * 16 + b_r) * 80 + (b_c + ko) * 2;
                ldsm4(bd, b[2 * p][0], b[2 * p][1], b[2 * p + 1][0], b[2 * p + 1][1]);
            }
            // pass 1: hi*hi
#pragma unroll
            for (int mt = 0; mt < 4; mt++)
#pragma unroll
                for (int nt = 0; nt < 8; nt++) mma16816(acc[mt][nt], ah[mt], b[nt]);
            // pass 2: lo*hi
#pragma unroll
            for (int mt = 0; mt < 4; mt++)
#pragma unroll
                for (int nt = 0; nt < 8; nt++) mma16816(acc[mt][nt], al[mt], b[nt]);
            // pass 3: hi*lo
#pragma unroll
            for (int p = 0; p < 4; p++) {
                const uint32_t bd = st + 2 * A_OP + B_OP +
                                    (warp_n * 64 + p * 16 + b_r) * 80 + (b_c + ko) * 2;
                ldsm4(bd, b[2 * p][0], b[2 * p][1], b[2 * p + 1][0], b[2 * p + 1][1]);
            }
#pragma unroll
            for (int mt = 0; mt < 4; mt++)
#pragma unroll
                for (int nt = 0; nt < 8; nt++) mma16816(acc[mt][nt], ah[mt], b[nt]);
        }
        if (++stage >= NSTAGE) stage = 0;
    }

    // epilogue
    const int g2 = lane >> 2, t2 = lane & 3;
#pragma unroll
    for (int mt = 0; mt < 4; mt++) {
        const int row0 = bm + warp_m * 64 + mt * 16 + g2;
#pragma unroll
        for (int nt = 0; nt < 8; nt++) {
            const int col = bn + warp_n * 64 + nt * 8 + 2 * t2;
            float2 v0 = make_float2(acc[mt][nt][0] * alpha, acc[mt][nt][1] * alpha);
            float2 v1 = make_float2(acc[mt][nt][2] * alpha, acc[mt][nt][3] * alpha);
            if (res) {
                float2 r0 = *(const float2*)(res + (size_t)row0 * N + col);
                float2 r1 = *(const float2*)(res + (size_t)(row0 + 8) * N + col);
                v0.x += r0.x; v0.y += r0.y; v1.x += r1.x; v1.y += r1.y;
            }
            *(float2*)(C + (size_t)row0 * N + col) = v0;
            *(float2*)(C + (size_t)(row0 + 8) * N + col) = v1;
        }
    }
}

// ------------------------- elementwise kernels ------------------------------
__device__ __forceinline__ void split1(float x, __nv_bfloat16* hp, __nv_bfloat16* lp) {
    __nv_bfloat16 h = __float2bfloat16(x);
    *hp = h;
    *lp = __float2bfloat16(x - __bfloat162float(h));
}

// 8 elems/thread, 16B stores
__global__ __launch_bounds__(256)
void k_split(const float* __restrict__ src, __nv_bfloat16* __restrict__ h,
             __nv_bfloat16* __restrict__ l, size_t n8)
{
    size_t i = (size_t)blockIdx.x * 256 + threadIdx.x;
    if (i >= n8) return;
    float4 v0 = ((const float4*)src)[2 * i];
    float4 v1 = ((const float4*)src)[2 * i + 1];
    __nv_bfloat16 hv[8], lv[8];
    split1(v0.x, &hv[0], &lv[0]);
    split1(v0.y, &hv[1], &lv[1]);
    split1(v0.z, &hv[2], &lv[2]);
    split1(v0.w, &hv[3], &lv[3]);
    split1(v1.x, &hv[4], &lv[4]);
    split1(v1.y, &hv[5], &lv[5]);
    split1(v1.z, &hv[6], &lv[6]);
    split1(v1.w, &hv[7], &lv[7]);
    *(uint4*)(h + 8 * i) = *(uint4*)hv;
    *(uint4*)(l + 8 * i) = *(uint4*)lv;
}

__global__ __launch_bounds__(256)
void k_rmsnorm_split(const float* __restrict__ x, const float* __restrict__ w,
                     __nv_bfloat16* __restrict__ oh, __nv_bfloat16* __restrict__ ol)
{
    const int row = blockIdx.x, tid = threadIdx.x;
    const float* xr = x + (size_t)row * D;
    float vals[8], local = 0.f;
#pragma unroll
    for (int i = 0; i < 8; i++) {
        float v = xr[tid + i * 256];
        vals[i] = v;
        local += v * v;
    }
#pragma unroll
    for (int o = 16; o > 0; o >>= 1)
        local += __shfl_xor_sync(0xffffffffu, local, o);
    __shared__ float sh[8];
    if ((tid & 31) == 0) sh[tid >> 5] = local;
    __syncthreads();
    if (tid == 0) {
        float s = 0.f;
#pragma unroll
        for (int i = 0; i < 8; i++) s += sh[i];
        sh[0] = rsqrtf(s / (float)D + EPSF);
    }
    __syncthreads();
    float scale = sh[0];
#pragma unroll
    for (int i = 0; i < 8; i++) {
        int j = tid + i * 256;
        split1(vals[i] * scale * w[j], &oh[(size_t)row * D + j], &ol[(size_t)row * D + j]);
    }
}

__global__ __launch_bounds__(256)
void k_rope_split(const float* __restrict__ qf, const float* __restrict__ cosb,
                  const float* __restrict__ sinb,
                  __nv_bfloat16* __restrict__ oh, __nv_bfloat16* __restrict__ ol)
{
    const int row = blockIdx.x, tid = threadIdx.x;
    const float* qr = qf + (size_t)row * D;
    const float* cr = cosb + (size_t)row * (D / 2);
    const float* sr = sinb + (size_t)row * (D / 2);
#pragma unroll
    for (int i = 0; i < 4; i++) {
        int j = tid + i * 256;
        float c = cr[j], s = sr[j];
        float x1 = qr[j], x2 = qr[j + D / 2];
        size_t o1 = (size_t)row * D + j, o2 = o1 + D / 2;
        split1(x1 * c - x2 * s, &oh[o1], &ol[o1]);
        split1(x1 * s + x2 * c, &oh[o2], &ol[o2]);
    }
}

__global__ __launch_bounds__(256)
void k_softmax_split(const float* __restrict__ scores,
                     __nv_bfloat16* __restrict__ ph, __nv_bfloat16* __restrict__ pl)
{
    const int row = blockIdx.x, tid = threadIdx.x;
    const float* p = scores + (size_t)row * S;
    float vals[16], m = -1e30f;
#pragma unroll
    for (int i = 0; i < 16; i++) {
        float v = p[tid + i * 256];
        vals[i] = v;
        m = fmaxf(m, v);
    }
#pragma unroll
    for (int o = 16; o > 0; o >>= 1)
        m = fmaxf(m, __shfl_xor_sync(0xffffffffu, m, o));
    __shared__ float sh[8];
    if ((tid & 31) == 0) sh[tid >> 5] = m;
    __syncthreads();
    if (tid == 0) {
        float mm = sh[0];
#pragma unroll
        for (int i = 1; i < 8; i++) mm = fmaxf(mm, sh[i]);
        sh[0] = mm;
    }
    __syncthreads();
    m = sh[0];
    __syncthreads();
    float sum = 0.f;
#pragma unroll
    for (int i = 0; i < 16; i++) {
        vals[i] = expf(vals[i] - m);
        sum += vals[i];
    }
#pragma unroll
    for (int o = 16; o > 0; o >>= 1)
        sum += __shfl_xor_sync(0xffffffffu, sum, o);
    if ((tid & 31) == 0) sh[tid >> 5] = sum;
    __syncthreads();
    if (tid == 0) {
        float ss = 0.f;
#pragma unroll
        for (int i = 0; i < 8; i++) ss += sh[i];
        sh[0] = 1.f / ss;
    }
    __syncthreads();
    float inv = sh[0];
#pragma unroll
    for (int i = 0; i < 16; i++) {
        size_t o = (size_t)row * S + tid + i * 256;
        split1(vals[i] * inv, &ph[o], &pl[o]);
    }
}

__global__ __launch_bounds__(256)
void k_transpose_split(const float* __restrict__ v,
                       __nv_bfloat16* __restrict__ th, __nv_bfloat16* __restrict__ tl)
{
    __shared__ float t[32][33];
    const int d0 = blockIdx.x * 32, s0 = blockIdx.y * 32;
    const int tx = threadIdx.x & 31, ty = threadIdx.x >> 5;
#pragma unroll
    for (int j = ty; j < 32; j += 8)
        t[j][tx] = v[(size_t)(s0 + j) * D + d0 + tx];
    __syncthreads();
#pragma unroll
    for (int j = ty; j < 32; j += 8) {
        float val = t[tx][j];
        size_t o = (size_t)(d0 + j) * S + s0 + tx;
        split1(val, &th[o], &tl[o]);
    }
}

__global__ __launch_bounds__(256)
void k_swiglu_split(const float* __restrict__ g, const float* __restrict__ u,
                    __nv_bfloat16* __restrict__ oh, __nv_bfloat16* __restrict__ ol)
{
    size_t i = (size_t)blockIdx.x * 256 + threadIdx.x;
    float4 gv = ((const float4*)g)[i];
    float4 uv = ((const float4*)u)[i];
    float r0 = gv.x / (1.f + expf(-gv.x)) * uv.x;
    float r1 = gv.y / (1.f + expf(-gv.y)) * uv.y;
    float r2 = gv.z / (1.f + expf(-gv.z)) * uv.z;
    float r3 = gv.w / (1.f + expf(-gv.w)) * uv.w;
    __nv_bfloat16 hv[4], lv[4];
    split1(r0, &hv[0], &lv[0]);
    split1(r1, &hv[1], &lv[1]);
    split1(r2, &hv[2], &lv[2]);
    split1(r3, &hv[3], &lv[3]);
    *(uint2*)(oh + 4 * i) = *(uint2*)hv;
    *(uint2*)(ol + 4 * i) = *(uint2*)lv;
}

// ------------------------- launch -------------------------------------------
static inline void split_launch(const float* src, __nv_bfloat16* h, __nv_bfloat16* l, size_t n) {
    size_t n8 = n / 8;
    k_split<<<(unsigned)((n8 + 255) / 256), 256>>>(src, h, l, n8);
}

extern "C" void kernel_launch(void* const* d_in, const int* in_sizes, int n_in,
                              void* d_out, int out_size)
{
    const float* x      = (const float*)d_in[0];
    const float* w_rn1  = (const float*)d_in[1];
    const float* wq     = (const float*)d_in[2];
    const float* wk     = (const float*)d_in[3];
    const float* wv     = (const float*)d_in[4];
    const float* wo     = (const float*)d_in[5];
    const float* w_rn2  = (const float*)d_in[6];
    const float* w_gate = (const float*)d_in[7];
    const float* w_up   = (const float*)d_in[8];
    const float* w_down = (const float*)d_in[9];
    const float* cosb   = (const float*)d_in[10];
    const float* sinb   = (const float*)d_in[11];
    float* out = (float*)d_out;

    static int smem_set = 0;
    if (!smem_set) {
        cudaFuncSetAttribute(gemm_mma, cudaFuncAttributeMaxDynamicSharedMemorySize, SMEMB);
        smem_set = 1;
    }

#define SYM(p, s) do { void* _t; cudaGetSymbolAddress(&_t, s); p = (decltype(p))_t; } while (0)
    __nv_bfloat16 *wq_h, *wq_l, *wk_h, *wk_l, *wv_h, *wv_l, *wo_h, *wo_l;
    __nv_bfloat16 *wg_h, *wg_l, *wu_h, *wu_l, *wd_h, *wd_l;
    __nv_bfloat16 *h_h, *h_l, *q_h, *q_l, *k_h, *k_l, *vt_h, *vt_l;
    __nv_bfloat16 *p_h, *p_l, *av_h, *av_l, *h2_h, *h2_l, *act_h, *act_l;
    float *qf, *kf, *vf, *sc, *avf, *x1, *gf, *uf;
    SYM(wq_h, g_wq_h); SYM(wq_l, g_wq_l); SYM(wk_h, g_wk_h); SYM(wk_l, g_wk_l);
    SYM(wv_h, g_wv_h); SYM(wv_l, g_wv_l); SYM(wo_h, g_wo_h); SYM(wo_l, g_wo_l);
    SYM(wg_h, g_wg_h); SYM(wg_l, g_wg_l); SYM(wu_h, g_wu_h); SYM(wu_l, g_wu_l);
    SYM(wd_h, g_wd_h); SYM(wd_l, g_wd_l);
    SYM(h_h, g_h_h);   SYM(h_l, g_h_l);   SYM(q_h, g_q_h);   SYM(q_l, g_q_l);
    SYM(k_h, g_k_h);   SYM(k_l, g_k_l);   SYM(vt_h, g_vt_h); SYM(vt_l, g_vt_l);
    SYM(p_h, g_p_h);   SYM(p_l, g_p_l);   SYM(av_h, g_av_h); SYM(av_l, g_av_l);
    SYM(h2_h, g_h2_h); SYM(h2_l, g_h2_l); SYM(act_h, g_act_h); SYM(act_l, g_act_l);
    SYM(qf, g_qf); SYM(kf, g_kf); SYM(vf, g_vf); SYM(sc, g_sc);
    SYM(avf, g_avf); SYM(x1, g_x1); SYM(gf, g_gf); SYM(uf, g_uf);
#undef SYM

    const float inv_scale = 1.f / sqrtf((float)D);

    // weight splits
    split_launch(wq, wq_h, wq_l, (size_t)D * D);
    split_launch(wk, wk_h, wk_l, (size_t)D * D);
    split_launch(wv, wv_h, wv_l, (size_t)D * D);
    split_launch(wo, wo_h, wo_l, (size_t)D * D);
    split_launch(w_gate, wg_h, wg_l, (size_t)FF * D);
    split_launch(w_up,   wu_h, wu_l, (size_t)FF * D);
    split_launch(w_down, wd_h, wd_l, (size_t)D * FF);

    // h = rmsnorm(x)*w_rn1, split
    k_rmsnorm_split<<<S, 256>>>(x, w_rn1, h_h, h_l);

    // grids: (N/128, M/256), M is always S=4096
    dim3 gDD(D / 128, S / 256);
    dim3 gSS(S / 128, S / 256);
    dim3 gFFd(FF / 128, S / 256);

    // q,k,v projections
    gemm_mma<<<gDD, 256, SMEMB>>>(h_h, h_l, wq_h, wq_l, qf, nullptr, S, D, D, 1.f);
    gemm_mma<<<gDD, 256, SMEMB>>>(h_h, h_l, wk_h, wk_l, kf, nullptr, S, D, D, 1.f);
    gemm_mma<<<gDD, 256, SMEMB>>>(h_h, h_l, wv_h, wv_l, vf, nullptr, S, D, D, 1.f);
    // rope + split
    k_rope_split<<<S, 256>>>(qf, cosb, sinb, q_h, q_l);
    k_rope_split<<<S, 256>>>(kf, cosb, sinb, k_h, k_l);
    // v transpose + split
    k_transpose_split<<<dim3(D / 32, S / 32), 256>>>(vf, vt_h, vt_l);
    // scores = q @ k^T / sqrt(D)
    gemm_mma<<<gSS, 256, SMEMB>>>(q_h, q_l, k_h, k_l, sc, nullptr, S, S, D, inv_scale);
    // softmax + split
    k_softmax_split<<<S, 256>>>(sc, p_h, p_l);
    // attnv = P @ V  (B = V^T [D,S])
    gemm_mma<<<gDD, 256, SMEMB>>>(p_h, p_l, vt_h, vt_l, avf, nullptr, S, D, S, 1.f);
    // split attnv
    split_launch(avf, av_h, av_l, (size_t)S * D);
    // x1 = x + attnv @ wo^T
    gemm_mma<<<gDD, 256, SMEMB>>>(av_h, av_l, wo_h, wo_l, x1, x, S, D, D, 1.f);
    // h2 = rmsnorm(x1)*w_rn2
    k_rmsnorm_split<<<S, 256>>>(x1, w_rn2, h2_h, h2_l);
    // gate / up
    gemm_mma<<<gFFd, 256, SMEMB>>>(h2_h, h2_l, wg_h, wg_l, gf, nullptr, S, FF, D, 1.f);
    gemm_mma<<<gFFd, 256, SMEMB>>>(h2_h, h2_l, wu_h, wu_l, uf, nullptr, S, FF, D, 1.f);
    // swiglu + split
    k_swiglu_split<<<(S * (FF / 4)) / 256, 256>>>(gf, uf, act_h, act_l);
    // out = x1 + act @ w_down^T
    gemm_mma<<<gDD, 256, SMEMB>>>(act_h, act_l, wd_h, wd_l, out, x1, S, D, FF, 1.f);
}

// round 8
// speedup vs baseline: 1.0190x; 1.0190x over previous
#include <cuda_runtime.h>
#include <cuda_bf16.h>
#include <stdint.h>
#include <math.h>

#define S  4096
#define D  2048
#define FF 8192
#define EPSF 1.1920929e-07f

#define KC 32                    // bf16 k per chunk
#define OPBYTES (128 * 80)       // one operand tile: 128 rows x 80B
#define STGB (4 * OPBYTES)       // Ah, Al, Bh, Bl
#define NSTAGE 2
#define SMEMB (NSTAGE * STGB)    // 81920 -> 2 CTAs/SM

// ------------------------- device scratch (no allocs allowed) ---------------
__device__ __nv_bfloat16 g_wq_h[(size_t)D*D],  g_wq_l[(size_t)D*D];
__device__ __nv_bfloat16 g_wk_h[(size_t)D*D],  g_wk_l[(size_t)D*D];
__device__ __nv_bfloat16 g_wv_h[(size_t)D*D],  g_wv_l[(size_t)D*D];
__device__ __nv_bfloat16 g_wo_h[(size_t)D*D],  g_wo_l[(size_t)D*D];
__device__ __nv_bfloat16 g_wg_h[(size_t)FF*D], g_wg_l[(size_t)FF*D];
__device__ __nv_bfloat16 g_wu_h[(size_t)FF*D], g_wu_l[(size_t)FF*D];
__device__ __nv_bfloat16 g_wd_h[(size_t)D*FF], g_wd_l[(size_t)D*FF];
__device__ __nv_bfloat16 g_h_h[(size_t)S*D],   g_h_l[(size_t)S*D];
__device__ __nv_bfloat16 g_q_h[(size_t)S*D],   g_q_l[(size_t)S*D];
__device__ __nv_bfloat16 g_k_h[(size_t)S*D],   g_k_l[(size_t)S*D];
__device__ __nv_bfloat16 g_vt_h[(size_t)D*S],  g_vt_l[(size_t)D*S];
__device__ __nv_bfloat16 g_p_h[(size_t)S*S],   g_p_l[(size_t)S*S];
__device__ __nv_bfloat16 g_av_h[(size_t)S*D],  g_av_l[(size_t)S*D];
__device__ __nv_bfloat16 g_h2_h[(size_t)S*D],  g_h2_l[(size_t)S*D];
__device__ __nv_bfloat16 g_act_h[(size_t)S*FF],g_act_l[(size_t)S*FF];
__device__ float g_qf[(size_t)S*D];
__device__ float g_kf[(size_t)S*D];
__device__ float g_vf[(size_t)S*D];
__device__ float g_sc[(size_t)S*S];
__device__ float g_x1[(size_t)S*D];
__device__ float g_gf[(size_t)S*FF];
__device__ float g_uf[(size_t)S*FF];

// ------------------------- helpers ------------------------------------------
__device__ __forceinline__ uint32_t smem_u32(const void* p) {
    uint32_t a;
    asm("{ .reg .u64 t; cvta.to.shared.u64 t, %1; cvt.u32.u64 %0, t; }"
        : "=r"(a) : "l"(p));
    return a;
}

__device__ __forceinline__ void cpasync16(uint32_t dst, const void* src) {
    asm volatile("cp.async.cg.shared.global [%0], [%1], 16;"
                 :: "r"(dst), "l"(src) : "memory");
}

__device__ __forceinline__ void ldsm4(uint32_t addr, uint32_t& r0, uint32_t& r1,
                                      uint32_t& r2, uint32_t& r3) {
    asm volatile("ldmatrix.sync.aligned.m8n8.x4.shared.b16 {%0,%1,%2,%3}, [%4];"
                 : "=r"(r0), "=r"(r1), "=r"(r2), "=r"(r3) : "r"(addr));
}

__device__ __forceinline__ void mma16816(float* c, const uint32_t* a, const uint32_t* b) {
    asm volatile("mma.sync.aligned.m16n8k16.row.col.f32.bf16.bf16.f32 "
                 "{%0,%1,%2,%3}, {%4,%5,%6,%7}, {%8,%9}, {%0,%1,%2,%3};"
                 : "+f"(c[0]), "+f"(c[1]), "+f"(c[2]), "+f"(c[3])
                 : "r"(a[0]), "r"(a[1]), "r"(a[2]), "r"(a[3]),
                   "r"(b[0]), "r"(b[1]));
}

__device__ __forceinline__ void split1(float x, __nv_bfloat16* hp, __nv_bfloat16* lp) {
    __nv_bfloat16 h = __float2bfloat16(x);
    *hp = h;
    *lp = __float2bfloat16(x - __bfloat162float(h));
}

__device__ __forceinline__ uint32_t pack_bf2(float a, float b) {
    __nv_bfloat162 t = __floats2bfloat162_rn(a, b);
    return *(uint32_t*)&t;
}

// ------------------------- tensor-core split GEMM ----------------------------
// OM=0: C fp32 (+optional res).  OM=1: write bf16 hi/lo split pair (oh/ol).
template <int OM>
__global__ __launch_bounds__(256, 2)
void gemm_mma(const __nv_bfloat16* __restrict__ Ah, const __nv_bfloat16* __restrict__ Al,
              const __nv_bfloat16* __restrict__ Bh, const __nv_bfloat16* __restrict__ Bl,
              float* __restrict__ C, const float* __restrict__ res,
              __nv_bfloat16* __restrict__ oh, __nv_bfloat16* __restrict__ ol,
              int M, int N, int K, float alpha)
{
    extern __shared__ __align__(128) char smem[];
    const int tid = threadIdx.x;
    const int wid = tid >> 5, lane = tid & 31;
    const int warp_m = wid & 3, warp_n = wid >> 2;
    const int bm = blockIdx.y * 128, bn = blockIdx.x * 128;
    const uint32_t sb = smem_u32(smem);
    const int nch = K / KC;

    float acc[2][8][4];
#pragma unroll
    for (int mt = 0; mt < 2; mt++)
#pragma unroll
        for (int nt = 0; nt < 8; nt++)
#pragma unroll
            for (int e = 0; e < 4; e++) acc[mt][nt][e] = 0.f;

    const int lrow = tid >> 2;
    const int lc   = tid & 3;

    auto issue = [&](int stage, int chunk) {
        const int k0 = chunk * KC;
#pragma unroll
        for (int r = 0; r < 2; r++) {
            const int row = lrow + r * 64;
            const uint32_t d = sb + stage * STGB + row * 80 + lc * 16;
            const size_t ga = (size_t)(bm + row) * K + k0 + lc * 8;
            const size_t gb = (size_t)(bn + row) * K + k0 + lc * 8;
            cpasync16(d,               Ah + ga);
            cpasync16(d + OPBYTES,     Al + ga);
            cpasync16(d + 2 * OPBYTES, Bh + gb);
            cpasync16(d + 3 * OPBYTES, Bl + gb);
        }
    };

    issue(0, 0);
    asm volatile("cp.async.commit_group;" ::: "memory");

    const int quad = lane >> 3, l8 = lane & 7;
    const int a_r = (quad & 1) * 8 + l8;
    const int a_c = (quad >> 1) * 8;
    const int b_r = (quad >> 1) * 8 + l8;
    const int b_c = (quad & 1) * 8;

    for (int i = 0; i < nch; i++) {
        asm volatile("cp.async.wait_group 0;" ::: "memory");
        __syncthreads();
        if (i + 1 < nch) issue((i + 1) & (NSTAGE - 1), i + 1);
        asm volatile("cp.async.commit_group;" ::: "memory");

        const uint32_t st = sb + (i & (NSTAGE - 1)) * STGB;
#pragma unroll
        for (int ks = 0; ks < 2; ks++) {
            const int ko = ks * 16;
            uint32_t ah[2][4], al[2][4], b[8][2];
#pragma unroll
            for (int mt = 0; mt < 2; mt++) {
                const uint32_t ad = st + (warp_m * 32 + mt * 16 + a_r) * 80 + (a_c + ko) * 2;
                ldsm4(ad,            ah[mt][0], ah[mt][1], ah[mt][2], ah[mt][3]);
                ldsm4(ad + OPBYTES,  al[mt][0], al[mt][1], al[mt][2], al[mt][3]);
            }
#pragma unroll
            for (int p = 0; p < 4; p++) {
                const uint32_t bd = st + 2 * OPBYTES +
                                    (warp_n * 64 + p * 16 + b_r) * 80 + (b_c + ko) * 2;
                ldsm4(bd, b[2 * p][0], b[2 * p][1], b[2 * p + 1][0], b[2 * p + 1][1]);
            }
#pragma unroll
            for (int mt = 0; mt < 2; mt++)
#pragma unroll
                for (int nt = 0; nt < 8; nt++) mma16816(acc[mt][nt], ah[mt], b[nt]);
#pragma unroll
            for (int mt = 0; mt < 2; mt++)
#pragma unroll
                for (int nt = 0; nt < 8; nt++) mma16816(acc[mt][nt], al[mt], b[nt]);
#pragma unroll
            for (int p = 0; p < 4; p++) {
                const uint32_t bd = st + 3 * OPBYTES +
                                    (warp_n * 64 + p * 16 + b_r) * 80 + (b_c + ko) * 2;
                ldsm4(bd, b[2 * p][0], b[2 * p][1], b[2 * p + 1][0], b[2 * p + 1][1]);
            }
#pragma unroll
            for (int mt = 0; mt < 2; mt++)
#pragma unroll
                for (int nt = 0; nt < 8; nt++) mma16816(acc[mt][nt], ah[mt], b[nt]);
        }
    }

    // epilogue
    const int g2 = lane >> 2, t2 = lane & 3;
#pragma unroll
    for (int mt = 0; mt < 2; mt++) {
        const int row0 = bm + warp_m * 32 + mt * 16 + g2;
#pragma unroll
        for (int nt = 0; nt < 8; nt++) {
            const int col = bn + warp_n * 64 + nt * 8 + 2 * t2;
            float2 v0 = make_float2(acc[mt][nt][0] * alpha, acc[mt][nt][1] * alpha);
            float2 v1 = make_float2(acc[mt][nt][2] * alpha, acc[mt][nt][3] * alpha);
            if (OM == 0) {
                if (res) {
                    float2 r0 = *(const float2*)(res + (size_t)row0 * N + col);
                    float2 r1 = *(const float2*)(res + (size_t)(row0 + 8) * N + col);
                    v0.x += r0.x; v0.y += r0.y; v1.x += r1.x; v1.y += r1.y;
                }
                *(float2*)(C + (size_t)row0 * N + col) = v0;
                *(float2*)(C + (size_t)(row0 + 8) * N + col) = v1;
            } else {
                __nv_bfloat16 h0, l0, h1, l1;
                split1(v0.x, &h0, &l0); split1(v0.y, &h1, &l1);
                *(uint32_t*)(oh + (size_t)row0 * N + col) = ((uint32_t*)&h0, (uint32_t)(*(uint16_t*)&h0) | ((uint32_t)(*(uint16_t*)&h1) << 16));
                *(uint32_t*)(ol + (size_t)row0 * N + col) = (uint32_t)(*(uint16_t*)&l0) | ((uint32_t)(*(uint16_t*)&l1) << 16);
                split1(v1.x, &h0, &l0); split1(v1.y, &h1, &l1);
                *(uint32_t*)(oh + (size_t)(row0 + 8) * N + col) = (uint32_t)(*(uint16_t*)&h0) | ((uint32_t)(*(uint16_t*)&h1) << 16);
                *(uint32_t*)(ol + (size_t)(row0 + 8) * N + col) = (uint32_t)(*(uint16_t*)&l0) | ((uint32_t)(*(uint16_t*)&l1) << 16);
            }
        }
    }
}

// ------------------------- elementwise kernels ------------------------------
// 16 elems/thread, 4 independent float4 loads
__global__ __launch_bounds__(256)
void k_split(const float* __restrict__ src, __nv_bfloat16* __restrict__ h,
             __nv_bfloat16* __restrict__ l, size_t n16)
{
    size_t i = (size_t)blockIdx.x * 256 + threadIdx.x;
    if (i >= n16) return;
    float4 v[4];
#pragma unroll
    for (int j = 0; j < 4; j++) v[j] = ((const float4*)src)[4 * i + j];
    __nv_bfloat16 hv[16], lv[16];
#pragma unroll
    for (int j = 0; j < 4; j++) {
        split1(v[j].x, &hv[4 * j + 0], &lv[4 * j + 0]);
        split1(v[j].y, &hv[4 * j + 1], &lv[4 * j + 1]);
        split1(v[j].z, &hv[4 * j + 2], &lv[4 * j + 2]);
        split1(v[j].w, &hv[4 * j + 3], &lv[4 * j + 3]);
    }
    *(uint4*)(h + 16 * i)     = *(uint4*)hv;
    *(uint4*)(h + 16 * i + 8) = *(uint4*)(hv + 8);
    *(uint4*)(l + 16 * i)     = *(uint4*)lv;
    *(uint4*)(l + 16 * i + 8) = *(uint4*)(lv + 8);
}

__global__ __launch_bounds__(256)
void k_rmsnorm_split(const float* __restrict__ x, const float* __restrict__ w,
                     __nv_bfloat16* __restrict__ oh, __nv_bfloat16* __restrict__ ol)
{
    const int row = blockIdx.x, tid = threadIdx.x;
    const float* xr = x + (size_t)row * D;
    float vals[8], local = 0.f;
#pragma unroll
    for (int i = 0; i < 8; i++) {
        float v = xr[tid + i * 256];
        vals[i] = v;
        local += v * v;
    }
#pragma unroll
    for (int o = 16; o > 0; o >>= 1)
        local += __shfl_xor_sync(0xffffffffu, local, o);
    __shared__ float sh[8];
    if ((tid & 31) == 0) sh[tid >> 5] = local;
    __syncthreads();
    if (tid == 0) {
        float s = 0.f;
#pragma unroll
        for (int i = 0; i < 8; i++) s += sh[i];
        sh[0] = rsqrtf(s / (float)D + EPSF);
    }
    __syncthreads();
    float scale = sh[0];
#pragma unroll
    for (int i = 0; i < 8; i++) {
        int j = tid + i * 256;
        split1(vals[i] * scale * w[j], &oh[(size_t)row * D + j], &ol[(size_t)row * D + j]);
    }
}

__global__ __launch_bounds__(256)
void k_rope_split(const float* __restrict__ qf, const float* __restrict__ cosb,
                  const float* __restrict__ sinb,
                  __nv_bfloat16* __restrict__ oh, __nv_bfloat16* __restrict__ ol)
{
    const int row = blockIdx.x, tid = threadIdx.x;
    const float* qr = qf + (size_t)row * D;
    const float* cr = cosb + (size_t)row * (D / 2);
    const float* sr = sinb + (size_t)row * (D / 2);
#pragma unroll
    for (int i = 0; i < 4; i++) {
        int j = tid + i * 256;
        float c = cr[j], s = sr[j];
        float x1 = qr[j], x2 = qr[j + D / 2];
        size_t o1 = (size_t)row * D + j, o2 = o1 + D / 2;
        split1(x1 * c - x2 * s, &oh[o1], &ol[o1]);
        split1(x1 * s + x2 * c, &oh[o2], &ol[o2]);
    }
}

__global__ __launch_bounds__(256)
void k_softmax_split(const float* __restrict__ scores,
                     __nv_bfloat16* __restrict__ ph, __nv_bfloat16* __restrict__ pl)
{
    const int row = blockIdx.x, tid = threadIdx.x;
    const float* p = scores + (size_t)row * S;
    float vals[16], m = -1e30f;
#pragma unroll
    for (int i = 0; i < 16; i++) {
        float v = p[tid + i * 256];
        vals[i] = v;
        m = fmaxf(m, v);
    }
#pragma unroll
    for (int o = 16; o > 0; o >>= 1)
        m = fmaxf(m, __shfl_xor_sync(0xffffffffu, m, o));
    __shared__ float sh[8];
    if ((tid & 31) == 0) sh[tid >> 5] = m;
    __syncthreads();
    if (tid == 0) {
        float mm = sh[0];
#pragma unroll
        for (int i = 1; i < 8; i++) mm = fmaxf(mm, sh[i]);
        sh[0] = mm;
    }
    __syncthreads();
    m = sh[0];
    __syncthreads();
    float sum = 0.f;
#pragma unroll
    for (int i = 0; i < 16; i++) {
        vals[i] = expf(vals[i] - m);
        sum += vals[i];
    }
#pragma unroll
    for (int o = 16; o > 0; o >>= 1)
        sum += __shfl_xor_sync(0xffffffffu, sum, o);
    if ((tid & 31) == 0) sh[tid >> 5] = sum;
    __syncthreads();
    if (tid == 0) {
        float ss = 0.f;
#pragma unroll
        for (int i = 0; i < 8; i++) ss += sh[i];
        sh[0] = 1.f / ss;
    }
    __syncthreads();
    float inv = sh[0];
#pragma unroll
    for (int i = 0; i < 16; i++) {
        size_t o = (size_t)row * S + tid + i * 256;
        split1(vals[i] * inv, &ph[o], &pl[o]);
    }
}

__global__ __launch_bounds__(256)
void k_transpose_split(const float* __restrict__ v,
                       __nv_bfloat16* __restrict__ th, __nv_bfloat16* __restrict__ tl)
{
    __shared__ float t[32][33];
    const int d0 = blockIdx.x * 32, s0 = blockIdx.y * 32;
    const int tx = threadIdx.x & 31, ty = threadIdx.x >> 5;
#pragma unroll
    for (int j = ty; j < 32; j += 8)
        t[j][tx] = v[(size_t)(s0 + j) * D + d0 + tx];
    __syncthreads();
#pragma unroll
    for (int j = ty; j < 32; j += 8) {
        float val = t[tx][j];
        size_t o = (size_t)(d0 + j) * S + s0 + tx;
        split1(val, &th[o], &tl[o]);
    }
}

__global__ __launch_bounds__(256)
void k_swiglu_split(const float* __restrict__ g, const float* __restrict__ u,
                    __nv_bfloat16* __restrict__ oh, __nv_bfloat16* __restrict__ ol)
{
    size_t i = (size_t)blockIdx.x * 256 + threadIdx.x;
    float4 gv = ((const float4*)g)[i];
    float4 uv = ((const float4*)u)[i];
    float r0 = gv.x / (1.f + expf(-gv.x)) * uv.x;
    float r1 = gv.y / (1.f + expf(-gv.y)) * uv.y;
    float r2 = gv.z / (1.f + expf(-gv.z)) * uv.z;
    float r3 = gv.w / (1.f + expf(-gv.w)) * uv.w;
    __nv_bfloat16 hv[4], lv[4];
    split1(r0, &hv[0], &lv[0]);
    split1(r1, &hv[1], &lv[1]);
    split1(r2, &hv[2], &lv[2]);
    split1(r3, &hv[3], &lv[3]);
    *(uint2*)(oh + 4 * i) = *(uint2*)hv;
    *(uint2*)(ol + 4 * i) = *(uint2*)lv;
}

// ------------------------- launch -------------------------------------------
static inline void split_launch(const float* src, __nv_bfloat16* h, __nv_bfloat16* l, size_t n) {
    size_t n16 = n / 16;
    k_split<<<(unsigned)((n16 + 255) / 256), 256>>>(src, h, l, n16);
}

extern "C" void kernel_launch(void* const* d_in, const int* in_sizes, int n_in,
                              void* d_out, int out_size)
{
    const float* x      = (const float*)d_in[0];
    const float* w_rn1  = (const float*)d_in[1];
    const float* wq     = (const float*)d_in[2];
    const float* wk     = (const float*)d_in[3];
    const float* wv     = (const float*)d_in[4];
    const float* wo     = (const float*)d_in[5];
    const float* w_rn2  = (const float*)d_in[6];
    const float* w_gate = (const float*)d_in[7];
    const float* w_up   = (const float*)d_in[8];
    const float* w_down = (const float*)d_in[9];
    const float* cosb   = (const float*)d_in[10];
    const float* sinb   = (const float*)d_in[11];
    float* out = (float*)d_out;

    static int smem_set = 0;
    if (!smem_set) {
        cudaFuncSetAttribute(gemm_mma<0>, cudaFuncAttributeMaxDynamicSharedMemorySize, SMEMB);
        cudaFuncSetAttribute(gemm_mma<1>, cudaFuncAttributeMaxDynamicSharedMemorySize, SMEMB);
        smem_set = 1;
    }

#define SYM(p, s) do { void* _t; cudaGetSymbolAddress(&_t, s); p = (decltype(p))_t; } while (0)
    __nv_bfloat16 *wq_h, *wq_l, *wk_h, *wk_l, *wv_h, *wv_l, *wo_h, *wo_l;
    __nv_bfloat16 *wg_h, *wg_l, *wu_h, *wu_l, *wd_h, *wd_l;
    __nv_bfloat16 *h_h, *h_l, *q_h, *q_l, *k_h, *k_l, *vt_h, *vt_l;
    __nv_bfloat16 *p_h, *p_l, *av_h, *av_l, *h2_h, *h2_l, *act_h, *act_l;
    float *qf, *kf, *vf, *sc, *x1, *gf, *uf;
    SYM(wq_h, g_wq_h); SYM(wq_l, g_wq_l); SYM(wk_h, g_wk_h); SYM(wk_l, g_wk_l);
    SYM(wv_h, g_wv_h); SYM(wv_l, g_wv_l); SYM(wo_h, g_wo_h); SYM(wo_l, g_wo_l);
    SYM(wg_h, g_wg_h); SYM(wg_l, g_wg_l); SYM(wu_h, g_wu_h); SYM(wu_l, g_wu_l);
    SYM(wd_h, g_wd_h); SYM(wd_l, g_wd_l);
    SYM(h_h, g_h_h);   SYM(h_l, g_h_l);   SYM(q_h, g_q_h);   SYM(q_l, g_q_l);
    SYM(k_h, g_k_h);   SYM(k_l, g_k_l);   SYM(vt_h, g_vt_h); SYM(vt_l, g_vt_l);
    SYM(p_h, g_p_h);   SYM(p_l, g_p_l);   SYM(av_h, g_av_h); SYM(av_l, g_av_l);
    SYM(h2_h, g_h2_h); SYM(h2_l, g_h2_l); SYM(act_h, g_act_h); SYM(act_l, g_act_l);
    SYM(qf, g_qf); SYM(kf, g_kf); SYM(vf, g_vf); SYM(sc, g_sc);
    SYM(x1, g_x1); SYM(gf, g_gf); SYM(uf, g_uf);
#undef SYM

    const float inv_scale = 1.f / sqrtf((float)D);

    dim3 gDD(D / 128, S / 128);
    dim3 gSS(S / 128, S / 128);
    dim3 gFFd(FF / 128, S / 128);

    // launches 0-4: qkv/o weight splits + rmsnorm (so launch #5 is a GEMM for ncu)
    split_launch(wq, wq_h, wq_l, (size_t)D * D);
    split_launch(wk, wk_h, wk_l, (size_t)D * D);
    split_launch(wv, wv_h, wv_l, (size_t)D * D);
    split_launch(wo, wo_h, wo_l, (size_t)D * D);
    k_rmsnorm_split<<<S, 256>>>(x, w_rn1, h_h, h_l);
    // launch 5: Q GEMM  <-- ncu -s 5 -c 1 captures this
    gemm_mma<0><<<gDD, 256, SMEMB>>>(h_h, h_l, wq_h, wq_l, qf, nullptr, nullptr, nullptr, S, D, D, 1.f);
    gemm_mma<0><<<gDD, 256, SMEMB>>>(h_h, h_l, wk_h, wk_l, kf, nullptr, nullptr, nullptr, S, D, D, 1.f);
    gemm_mma<0><<<gDD, 256, SMEMB>>>(h_h, h_l, wv_h, wv_l, vf, nullptr, nullptr, nullptr, S, D, D, 1.f);
    // ffn weight splits (overlap-friendly position)
    split_launch(w_gate, wg_h, wg_l, (size_t)FF * D);
    split_launch(w_up,   wu_h, wu_l, (size_t)FF * D);
    split_launch(w_down, wd_h, wd_l, (size_t)D * FF);
    // rope + split
    k_rope_split<<<S, 256>>>(qf, cosb, sinb, q_h, q_l);
    k_rope_split<<<S, 256>>>(kf, cosb, sinb, k_h, k_l);
    // v transpose + split
    k_transpose_split<<<dim3(D / 32, S / 32), 256>>>(vf, vt_h, vt_l);
    // scores = q @ k^T / sqrt(D)
    gemm_mma<0><<<gSS, 256, SMEMB>>>(q_h, q_l, k_h, k_l, sc, nullptr, nullptr, nullptr, S, S, D, inv_scale);
    // softmax + split
    k_softmax_split<<<S, 256>>>(sc, p_h, p_l);
    // attnv = P @ V, epilogue writes bf16 hi/lo directly (no separate split)
    gemm_mma<1><<<gDD, 256, SMEMB>>>(p_h, p_l, vt_h, vt_l, nullptr, nullptr, av_h, av_l, S, D, S, 1.f);
    // x1 = x + attnv @ wo^T
    gemm_mma<0><<<gDD, 256, SMEMB>>>(av_h, av_l, wo_h, wo_l, x1, x, nullptr, nullptr, S, D, D, 1.f);
    // h2 = rmsnorm(x1)*w_rn2
    k_rmsnorm_split<<<S, 256>>>(x1, w_rn2, h2_h, h2_l);
    // gate / up
    gemm_mma<0><<<gFFd, 256, SMEMB>>>(h2_h, h2_l, wg_h, wg_l, gf, nullptr, nullptr, nullptr, S, FF, D, 1.f);
    gemm_mma<0><<<gFFd, 256, SMEMB>>>(h2_h, h2_l, wu_h, wu_l, uf, nullptr, nullptr, nullptr, S, FF, D, 1.f);
    // swiglu + split
    k_swiglu_split<<<(S * (FF / 4)) / 256, 256>>>(gf, uf, act_h, act_l);
    // out = x1 + act @ w_down^T
    gemm_mma<0><<<gDD, 256, SMEMB>>>(act_h, act_l, wd_h, wd_l, out, x1, nullptr, nullptr, S, D, FF, 1.f);
}

// round 9
// speedup vs baseline: 1.0937x; 1.0733x over previous
#include <cuda_runtime.h>
#include <cuda_bf16.h>
#include <stdint.h>
#include <math.h>

#define S  4096
#define D  2048
#define FF 8192
#define EPSF 1.1920929e-07f

#define KC 32                    // bf16 k per chunk
#define OPBYTES (128 * 80)       // one operand tile: 128 rows x 80B
#define STGB (4 * OPBYTES)       // Ah, Al, Bh, Bl slots
#define NSTAGE 2
#define SMEMB (NSTAGE * STGB)    // 81920 -> 2 CTAs/SM

// ------------------------- device scratch (no allocs allowed) ---------------
__device__ __nv_bfloat16 g_wq_h[(size_t)D*D],  g_wq_l[(size_t)D*D];
__device__ __nv_bfloat16 g_wk_h[(size_t)D*D],  g_wk_l[(size_t)D*D];
__device__ __nv_bfloat16 g_wv_h[(size_t)D*D],  g_wv_l[(size_t)D*D];
__device__ __nv_bfloat16 g_wo_h[(size_t)D*D],  g_wo_l[(size_t)D*D];
__device__ __nv_bfloat16 g_wg_h[(size_t)FF*D], g_wg_l[(size_t)FF*D];
__device__ __nv_bfloat16 g_wu_h[(size_t)FF*D], g_wu_l[(size_t)FF*D];
__device__ __nv_bfloat16 g_wd_h[(size_t)D*FF], g_wd_l[(size_t)D*FF];
__device__ __nv_bfloat16 g_h_h[(size_t)S*D],   g_h_l[(size_t)S*D];
__device__ __nv_bfloat16 g_q_h[(size_t)S*D],   g_q_l[(size_t)S*D];
__device__ __nv_bfloat16 g_k_h[(size_t)S*D],   g_k_l[(size_t)S*D];
__device__ __nv_bfloat16 g_vt_h[(size_t)D*S],  g_vt_l[(size_t)D*S];
__device__ __nv_bfloat16 g_p_h[(size_t)S*S],   g_p_l[(size_t)S*S];
__device__ __nv_bfloat16 g_av_h[(size_t)S*D],  g_av_l[(size_t)S*D];
__device__ __nv_bfloat16 g_h2_h[(size_t)S*D],  g_h2_l[(size_t)S*D];
__device__ __nv_bfloat16 g_act_h[(size_t)S*FF],g_act_l[(size_t)S*FF];
__device__ float g_qf[(size_t)S*D];
__device__ float g_kf[(size_t)S*D];
__device__ float g_vf[(size_t)S*D];
__device__ float g_sc[(size_t)S*S];
__device__ float g_x1[(size_t)S*D];
__device__ float g_gf[(size_t)S*FF];

// ------------------------- helpers ------------------------------------------
__device__ __forceinline__ uint32_t smem_u32(const void* p) {
    uint32_t a;
    asm("{ .reg .u64 t; cvta.to.shared.u64 t, %1; cvt.u32.u64 %0, t; }"
        : "=r"(a) : "l"(p));
    return a;
}

__device__ __forceinline__ void cpasync16(uint32_t dst, const void* src) {
    asm volatile("cp.async.cg.shared.global [%0], [%1], 16;"
                 :: "r"(dst), "l"(src) : "memory");
}

__device__ __forceinline__ void ldsm4(uint32_t addr, uint32_t& r0, uint32_t& r1,
                                      uint32_t& r2, uint32_t& r3) {
    asm volatile("ldmatrix.sync.aligned.m8n8.x4.shared.b16 {%0,%1,%2,%3}, [%4];"
                 : "=r"(r0), "=r"(r1), "=r"(r2), "=r"(r3) : "r"(addr));
}

__device__ __forceinline__ void mma16816(float* c, const uint32_t* a, const uint32_t* b) {
    asm volatile("mma.sync.aligned.m16n8k16.row.col.f32.bf16.bf16.f32 "
                 "{%0,%1,%2,%3}, {%4,%5,%6,%7}, {%8,%9}, {%0,%1,%2,%3};"
                 : "+f"(c[0]), "+f"(c[1]), "+f"(c[2]), "+f"(c[3])
                 : "r"(a[0]), "r"(a[1]), "r"(a[2]), "r"(a[3]),
                   "r"(b[0]), "r"(b[1]));
}

__device__ __forceinline__ void split1(float x, __nv_bfloat16* hp, __nv_bfloat16* lp) {
    __nv_bfloat16 h = __float2bfloat16(x);
    *hp = h;
    *lp = __float2bfloat16(x - __bfloat162float(h));
}

__device__ __forceinline__ void store_split2(__nv_bfloat16* oh, __nv_bfloat16* ol,
                                             size_t off, float a, float b) {
    __nv_bfloat16 ha, la, hb, lb;
    split1(a, &ha, &la);
    split1(b, &hb, &lb);
    *(uint32_t*)(oh + off) = (uint32_t)(*(uint16_t*)&ha) | ((uint32_t)(*(uint16_t*)&hb) << 16);
    *(uint32_t*)(ol + off) = (uint32_t)(*(uint16_t*)&la) | ((uint32_t)(*(uint16_t*)&lb) << 16);
}

// ------------------------- tensor-core split GEMM ----------------------------
// C[M,N] = alpha * A_split @ B_split^T.
// NPASS=3: Ah*Bh + Al*Bh + Ah*Bl (eps^2 accuracy). NPASS=2: (Ah+Al)*Bh = A*Bh.
// OM=0: fp32 out (+res). OM=1: bf16 hi/lo split out. OM=2: silu(res)*acc, bf16 split out.
template <int OM, int NPASS>
__global__ __launch_bounds__(256, 2)
void gemm_mma(const __nv_bfloat16* __restrict__ Ah, const __nv_bfloat16* __restrict__ Al,
              const __nv_bfloat16* __restrict__ Bh, const __nv_bfloat16* __restrict__ Bl,
              float* __restrict__ C, const float* __restrict__ res,
              __nv_bfloat16* __restrict__ oh, __nv_bfloat16* __restrict__ ol,
              int M, int N, int K, float alpha)
{
    extern __shared__ __align__(128) char smem[];
    const int tid = threadIdx.x;
    const int wid = tid >> 5, lane = tid & 31;
    const int warp_m = wid & 3, warp_n = wid >> 2;
    const int bm = blockIdx.y * 128, bn = blockIdx.x * 128;
    const uint32_t sb = smem_u32(smem);
    const int nch = K / KC;

    float acc[2][8][4];
#pragma unroll
    for (int mt = 0; mt < 2; mt++)
#pragma unroll
        for (int nt = 0; nt < 8; nt++)
#pragma unroll
            for (int e = 0; e < 4; e++) acc[mt][nt][e] = 0.f;

    const int lrow = tid >> 2;
    const int lc   = tid & 3;

    auto issue = [&](int stage, int chunk) {
        const int k0 = chunk * KC;
#pragma unroll
        for (int r = 0; r < 2; r++) {
            const int row = lrow + r * 64;
            const uint32_t d = sb + stage * STGB + row * 80 + lc * 16;
            const size_t ga = (size_t)(bm + row) * K + k0 + lc * 8;
            const size_t gb = (size_t)(bn + row) * K + k0 + lc * 8;
            cpasync16(d,               Ah + ga);
            cpasync16(d + OPBYTES,     Al + ga);
            cpasync16(d + 2 * OPBYTES, Bh + gb);
            if (NPASS == 3) cpasync16(d + 3 * OPBYTES, Bl + gb);
        }
    };

    issue(0, 0);
    asm volatile("cp.async.commit_group;" ::: "memory");

    const int quad = lane >> 3, l8 = lane & 7;
    const int a_r = (quad & 1) * 8 + l8;
    const int a_c = (quad >> 1) * 8;
    const int b_r = (quad >> 1) * 8 + l8;
    const int b_c = (quad & 1) * 8;

    for (int i = 0; i < nch; i++) {
        asm volatile("cp.async.wait_group 0;" ::: "memory");
        __syncthreads();
        if (i + 1 < nch) issue((i + 1) & (NSTAGE - 1), i + 1);
        asm volatile("cp.async.commit_group;" ::: "memory");

        const uint32_t st = sb + (i & (NSTAGE - 1)) * STGB;
#pragma unroll
        for (int ks = 0; ks < 2; ks++) {
            const int ko = ks * 16;
            uint32_t ah[2][4], al[2][4], b[8][2];
#pragma unroll
            for (int mt = 0; mt < 2; mt++) {
                const uint32_t ad = st + (warp_m * 32 + mt * 16 + a_r) * 80 + (a_c + ko) * 2;
                ldsm4(ad,            ah[mt][0], ah[mt][1], ah[mt][2], ah[mt][3]);
                ldsm4(ad + OPBYTES,  al[mt][0], al[mt][1], al[mt][2], al[mt][3]);
            }
#pragma unroll
            for (int p = 0; p < 4; p++) {
                const uint32_t bd = st + 2 * OPBYTES +
                                    (warp_n * 64 + p * 16 + b_r) * 80 + (b_c + ko) * 2;
                ldsm4(bd, b[2 * p][0], b[2 * p][1], b[2 * p + 1][0], b[2 * p + 1][1]);
            }
            // pass 1: hi*hi
#pragma unroll
            for (int mt = 0; mt < 2; mt++)
#pragma unroll
                for (int nt = 0; nt < 8; nt++) mma16816(acc[mt][nt], ah[mt], b[nt]);
            // pass 2: lo*hi
#pragma unroll
            for (int mt = 0; mt < 2; mt++)
#pragma unroll
                for (int nt = 0; nt < 8; nt++) mma16816(acc[mt][nt], al[mt], b[nt]);
            // pass 3: hi*lo
            if (NPASS == 3) {
#pragma unroll
                for (int p = 0; p < 4; p++) {
                    const uint32_t bd = st + 3 * OPBYTES +
                                        (warp_n * 64 + p * 16 + b_r) * 80 + (b_c + ko) * 2;
                    ldsm4(bd, b[2 * p][0], b[2 * p][1], b[2 * p + 1][0], b[2 * p + 1][1]);
                }
#pragma unroll
                for (int mt = 0; mt < 2; mt++)
#pragma unroll
                    for (int nt = 0; nt < 8; nt++) mma16816(acc[mt][nt], ah[mt], b[nt]);
            }
        }
    }

    // epilogue
    const int g2 = lane >> 2, t2 = lane & 3;
#pragma unroll
    for (int mt = 0; mt < 2; mt++) {
        const int row0 = bm + warp_m * 32 + mt * 16 + g2;
#pragma unroll
        for (int nt = 0; nt < 8; nt++) {
            const int col = bn + warp_n * 64 + nt * 8 + 2 * t2;
            float2 v0 = make_float2(acc[mt][nt][0] * alpha, acc[mt][nt][1] * alpha);
            float2 v1 = make_float2(acc[mt][nt][2] * alpha, acc[mt][nt][3] * alpha);
            if (OM == 0) {
                if (res) {
                    float2 r0 = *(const float2*)(res + (size_t)row0 * N + col);
                    float2 r1 = *(const float2*)(res + (size_t)(row0 + 8) * N + col);
                    v0.x += r0.x; v0.y += r0.y; v1.x += r1.x; v1.y += r1.y;
                }
                *(float2*)(C + (size_t)row0 * N + col) = v0;
                *(float2*)(C + (size_t)(row0 + 8) * N + col) = v1;
            } else if (OM == 1) {
                store_split2(oh, ol, (size_t)row0 * N + col, v0.x, v0.y);
                store_split2(oh, ol, (size_t)(row0 + 8) * N + col, v1.x, v1.y);
            } else {
                // OM == 2: act = silu(gate) * acc, gate read from res
                float2 ga = *(const float2*)(res + (size_t)row0 * N + col);
                float2 gb = *(const float2*)(res + (size_t)(row0 + 8) * N + col);
                float r0 = ga.x / (1.f + expf(-ga.x)) * v0.x;
                float r1 = ga.y / (1.f + expf(-ga.y)) * v0.y;
                float r2 = gb.x / (1.f + expf(-gb.x)) * v1.x;
                float r3 = gb.y / (1.f + expf(-gb.y)) * v1.y;
                store_split2(oh, ol, (size_t)row0 * N + col, r0, r1);
                store_split2(oh, ol, (size_t)(row0 + 8) * N + col, r2, r3);
            }
        }
    }
}

// ------------------------- elementwise kernels ------------------------------
// 16 elems/thread, 4 independent float4 loads
__global__ __launch_bounds__(256)
void k_split(const float* __restrict__ src, __nv_bfloat16* __restrict__ h,
             __nv_bfloat16* __restrict__ l, size_t n16)
{
    size_t i = (size_t)blockIdx.x * 256 + threadIdx.x;
    if (i >= n16) return;
    float4 v[4];
#pragma unroll
    for (int j = 0; j < 4; j++) v[j] = ((const float4*)src)[4 * i + j];
    __nv_bfloat16 hv[16], lv[16];
#pragma unroll
    for (int j = 0; j < 4; j++) {
        split1(v[j].x, &hv[4 * j + 0], &lv[4 * j + 0]);
        split1(v[j].y, &hv[4 * j + 1], &lv[4 * j + 1]);
        split1(v[j].z, &hv[4 * j + 2], &lv[4 * j + 2]);
        split1(v[j].w, &hv[4 * j + 3], &lv[4 * j + 3]);
    }
    *(uint4*)(h + 16 * i)     = *(uint4*)hv;
    *(uint4*)(h + 16 * i + 8) = *(uint4*)(hv + 8);
    *(uint4*)(l + 16 * i)     = *(uint4*)lv;
    *(uint4*)(l + 16 * i + 8) = *(uint4*)(lv + 8);
}

__global__ __launch_bounds__(256)
void k_rmsnorm_split(const float* __restrict__ x, const float* __restrict__ w,
                     __nv_bfloat16* __restrict__ oh, __nv_bfloat16* __restrict__ ol)
{
    const int row = blockIdx.x, tid = threadIdx.x;
    const float* xr = x + (size_t)row * D;
    float vals[8], local = 0.f;
#pragma unroll
    for (int i = 0; i < 8; i++) {
        float v = xr[tid + i * 256];
        vals[i] = v;
        local += v * v;
    }
#pragma unroll
    for (int o = 16; o > 0; o >>= 1)
        local += __shfl_xor_sync(0xffffffffu, local, o);
    __shared__ float sh[8];
    if ((tid & 31) == 0) sh[tid >> 5] = local;
    __syncthreads();
    if (tid == 0) {
        float s = 0.f;
#pragma unroll
        for (int i = 0; i < 8; i++) s += sh[i];
        sh[0] = rsqrtf(s / (float)D + EPSF);
    }
    __syncthreads();
    float scale = sh[0];
#pragma unroll
    for (int i = 0; i < 8; i++) {
        int j = tid + i * 256;
        split1(vals[i] * scale * w[j], &oh[(size_t)row * D + j], &ol[(size_t)row * D + j]);
    }
}

__global__ __launch_bounds__(256)
void k_rope_split(const float* __restrict__ qf, const float* __restrict__ cosb,
                  const float* __restrict__ sinb,
                  __nv_bfloat16* __restrict__ oh, __nv_bfloat16* __restrict__ ol)
{
    const int row = blockIdx.x, tid = threadIdx.x;
    const float* qr = qf + (size_t)row * D;
    const float* cr = cosb + (size_t)row * (D / 2);
    const float* sr = sinb + (size_t)row * (D / 2);
#pragma unroll
    for (int i = 0; i < 4; i++) {
        int j = tid + i * 256;
        float c = cr[j], s = sr[j];
        float x1 = qr[j], x2 = qr[j + D / 2];
        size_t o1 = (size_t)row * D + j, o2 = o1 + D / 2;
        split1(x1 * c - x2 * s, &oh[o1], &ol[o1]);
        split1(x1 * s + x2 * c, &oh[o2], &ol[o2]);
    }
}

__global__ __launch_bounds__(256)
void k_softmax_split(const float* __restrict__ scores,
                     __nv_bfloat16* __restrict__ ph, __nv_bfloat16* __restrict__ pl)
{
    const int row = blockIdx.x, tid = threadIdx.x;
    const float* p = scores + (size_t)row * S;
    float vals[16], m = -1e30f;
#pragma unroll
    for (int i = 0; i < 16; i++) {
        float v = p[tid + i * 256];
        vals[i] = v;
        m = fmaxf(m, v);
    }
#pragma unroll
    for (int o = 16; o > 0; o >>= 1)
        m = fmaxf(m, __shfl_xor_sync(0xffffffffu, m, o));
    __shared__ float sh[8];
    if ((tid & 31) == 0) sh[tid >> 5] = m;
    __syncthreads();
    if (tid == 0) {
        float mm = sh[0];
#pragma unroll
        for (int i = 1; i < 8; i++) mm = fmaxf(mm, sh[i]);
        sh[0] = mm;
    }
    __syncthreads();
    m = sh[0];
    __syncthreads();
    float sum = 0.f;
#pragma unroll
    for (int i = 0; i < 16; i++) {
        vals[i] = expf(vals[i] - m);
        sum += vals[i];
    }
#pragma unroll
    for (int o = 16; o > 0; o >>= 1)
        sum += __shfl_xor_sync(0xffffffffu, sum, o);
    if ((tid & 31) == 0) sh[tid >> 5] = sum;
    __syncthreads();
    if (tid == 0) {
        float ss = 0.f;
#pragma unroll
        for (int i = 0; i < 8; i++) ss += sh[i];
        sh[0] = 1.f / ss;
    }
    __syncthreads();
    float inv = sh[0];
#pragma unroll
    for (int i = 0; i < 16; i++) {
        size_t o = (size_t)row * S + tid + i * 256;
        split1(vals[i] * inv, &ph[o], &pl[o]);
    }
}

__global__ __launch_bounds__(256)
void k_transpose_split(const float* __restrict__ v,
                       __nv_bfloat16* __restrict__ th, __nv_bfloat16* __restrict__ tl)
{
    __shared__ float t[32][33];
    const int d0 = blockIdx.x * 32, s0 = blockIdx.y * 32;
    const int tx = threadIdx.x & 31, ty = threadIdx.x >> 5;
#pragma unroll
    for (int j = ty; j < 32; j += 8)
        t[j][tx] = v[(size_t)(s0 + j) * D + d0 + tx];
    __syncthreads();
#pragma unroll
    for (int j = ty; j < 32; j += 8) {
        float val = t[tx][j];
        size_t o = (size_t)(d0 + j) * S + s0 + tx;
        split1(val, &th[o], &tl[o]);
    }
}

// ------------------------- launch -------------------------------------------
static inline void split_launch(const float* src, __nv_bfloat16* h, __nv_bfloat16* l, size_t n) {
    size_t n16 = n / 16;
    k_split<<<(unsigned)((n16 + 255) / 256), 256>>>(src, h, l, n16);
}

extern "C" void kernel_launch(void* const* d_in, const int* in_sizes, int n_in,
                              void* d_out, int out_size)
{
    const float* x      = (const float*)d_in[0];
    const float* w_rn1  = (const float*)d_in[1];
    const float* wq     = (const float*)d_in[2];
    const float* wk     = (const float*)d_in[3];
    const float* wv     = (const float*)d_in[4];
    const float* wo     = (const float*)d_in[5];
    const float* w_rn2  = (const float*)d_in[6];
    const float* w_gate = (const float*)d_in[7];
    const float* w_up   = (const float*)d_in[8];
    const float* w_down = (const float*)d_in[9];
    const float* cosb   = (const float*)d_in[10];
    const float* sinb   = (const float*)d_in[11];
    float* out = (float*)d_out;

    static int smem_set = 0;
    if (!smem_set) {
        cudaFuncSetAttribute(gemm_mma<0,3>, cudaFuncAttributeMaxDynamicSharedMemorySize, SMEMB);
        cudaFuncSetAttribute(gemm_mma<0,2>, cudaFuncAttributeMaxDynamicSharedMemorySize, SMEMB);
        cudaFuncSetAttribute(gemm_mma<1,2>, cudaFuncAttributeMaxDynamicSharedMemorySize, SMEMB);
        cudaFuncSetAttribute(gemm_mma<2,3>, cudaFuncAttributeMaxDynamicSharedMemorySize, SMEMB);
        smem_set = 1;
    }

#define SYM(p, s) do { void* _t; cudaGetSymbolAddress(&_t, s); p = (decltype(p))_t; } while (0)
    __nv_bfloat16 *wq_h, *wq_l, *wk_h, *wk_l, *wv_h, *wv_l, *wo_h, *wo_l;
    __nv_bfloat16 *wg_h, *wg_l, *wu_h, *wu_l, *wd_h, *wd_l;
    __nv_bfloat16 *h_h, *h_l, *q_h, *q_l, *k_h, *k_l, *vt_h, *vt_l;
    __nv_bfloat16 *p_h, *p_l, *av_h, *av_l, *h2_h, *h2_l, *act_h, *act_l;
    float *qf, *kf, *vf, *sc, *x1, *gf;
    SYM(wq_h, g_wq_h); SYM(wq_l, g_wq_l); SYM(wk_h, g_wk_h); SYM(wk_l, g_wk_l);
    SYM(wv_h, g_wv_h); SYM(wv_l, g_wv_l); SYM(wo_h, g_wo_h); SYM(wo_l, g_wo_l);
    SYM(wg_h, g_wg_h); SYM(wg_l, g_wg_l); SYM(wu_h, g_wu_h); SYM(wu_l, g_wu_l);
    SYM(wd_h, g_wd_h); SYM(wd_l, g_wd_l);
    SYM(h_h, g_h_h);   SYM(h_l, g_h_l);   SYM(q_h, g_q_h);   SYM(q_l, g_q_l);
    SYM(k_h, g_k_h);   SYM(k_l, g_k_l);   SYM(vt_h, g_vt_h); SYM(vt_l, g_vt_l);
    SYM(p_h, g_p_h);   SYM(p_l, g_p_l);   SYM(av_h, g_av_h); SYM(av_l, g_av_l);
    SYM(h2_h, g_h2_h); SYM(h2_l, g_h2_l); SYM(act_h, g_act_h); SYM(act_l, g_act_l);
    SYM(qf, g_qf); SYM(kf, g_kf); SYM(vf, g_vf); SYM(sc, g_sc);
    SYM(x1, g_x1); SYM(gf, g_gf);
#undef SYM

    const float inv_scale = 1.f / sqrtf((float)D);

    dim3 gDD(D / 128, S / 128);
    dim3 gSS(S / 128, S / 128);
    dim3 gFFd(FF / 128, S / 128);

    // weight splits + first rmsnorm
    split_launch(wq, wq_h, wq_l, (size_t)D * D);
    split_launch(wk, wk_h, wk_l, (size_t)D * D);
    split_launch(wv, wv_h, wv_l, (size_t)D * D);
    split_launch(wo, wo_h, wo_l, (size_t)D * D);
    k_rmsnorm_split<<<S, 256>>>(x, w_rn1, h_h, h_l);
    // q,k,v projections (3-pass)
    gemm_mma<0,3><<<gDD, 256, SMEMB>>>(h_h, h_l, wq_h, wq_l, qf, nullptr, nullptr, nullptr, S, D, D, 1.f);
    gemm_mma<0,3><<<gDD, 256, SMEMB>>>(h_h, h_l, wk_h, wk_l, kf, nullptr, nullptr, nullptr, S, D, D, 1.f);
    gemm_mma<0,3><<<gDD, 256, SMEMB>>>(h_h, h_l, wv_h, wv_l, vf, nullptr, nullptr, nullptr, S, D, D, 1.f);
    // ffn weight splits
    split_launch(w_gate, wg_h, wg_l, (size_t)FF * D);
    split_launch(w_up,   wu_h, wu_l, (size_t)FF * D);
    split_launch(w_down, wd_h, wd_l, (size_t)D * FF);
    // rope + split
    k_rope_split<<<S, 256>>>(qf, cosb, sinb, q_h, q_l);
    k_rope_split<<<S, 256>>>(kf, cosb, sinb, k_h, k_l);
    // v transpose + split
    k_transpose_split<<<dim3(D / 32, S / 32), 256>>>(vf, vt_h, vt_l);
    // scores = q @ k^T / sqrt(D)   (2-pass: q full, k hi only)
    gemm_mma<0,2><<<gSS, 256, SMEMB>>>(q_h, q_l, k_h, k_l, sc, nullptr, nullptr, nullptr, S, S, D, inv_scale);
    // softmax + split
    k_softmax_split<<<S, 256>>>(sc, p_h, p_l);
    // attnv = P @ V  (2-pass: P full, V hi only), epilogue writes bf16 hi/lo
    gemm_mma<1,2><<<gDD, 256, SMEMB>>>(p_h, p_l, vt_h, vt_l, nullptr, nullptr, av_h, av_l, S, D, S, 1.f);
    // x1 = x + attnv @ wo^T  (3-pass)
    gemm_mma<0,3><<<gDD, 256, SMEMB>>>(av_h, av_l, wo_h, wo_l, x1, x, nullptr, nullptr, S, D, D, 1.f);
    // h2 = rmsnorm(x1)*w_rn2
    k_rmsnorm_split<<<S, 256>>>(x1, w_rn2, h2_h, h2_l);
    // gate (3-pass, fp32 out)
    gemm_mma<0,3><<<gFFd, 256, SMEMB>>>(h2_h, h2_l, wg_h, wg_l, gf, nullptr, nullptr, nullptr, S, FF, D, 1.f);
    // up (3-pass) with fused SwiGLU epilogue: act = silu(gf) * up, bf16 split out
    gemm_mma<2,3><<<gFFd, 256, SMEMB>>>(h2_h, h2_l, wu_h, wu_l, nullptr, gf, act_h, act_l, S, FF, D, 1.f);
    // out = x1 + act @ w_down^T  (3-pass)
    gemm_mma<0,3><<<gDD, 256, SMEMB>>>(act_h, act_l, wd_h, wd_l, out, x1, nullptr, nullptr, S, D, FF, 1.f);
}

// round 12
// speedup vs baseline: 1.2598x; 1.1518x over previous
#include <cuda_runtime.h>
#include <cuda_bf16.h>
#include <stdint.h>
#include <math.h>

#define S  4096
#define D  2048
#define FF 8192
#define EPSF 1.1920929e-07f

#define KC 32                    // bf16 k per chunk
#define OPBYTES (128 * 80)       // one operand tile: 128 rows x 80B
#define STGB (4 * OPBYTES)       // Ah, Al, Bh, Bl slots
#define NSTAGE 2
#define SMEMB (NSTAGE * STGB)    // 81920 -> 2 CTAs/SM

// ------------------------- device scratch (no allocs allowed) ---------------
__device__ __nv_bfloat16 g_wq_h[(size_t)D*D];
__device__ __nv_bfloat16 g_wk_h[(size_t)D*D];
__device__ __nv_bfloat16 g_wv_h[(size_t)D*D];
__device__ __nv_bfloat16 g_wo_h[(size_t)D*D];
__device__ __nv_bfloat16 g_wg_h[(size_t)FF*D], g_wg_l[(size_t)FF*D];
__device__ __nv_bfloat16 g_wu_h[(size_t)FF*D], g_wu_l[(size_t)FF*D];
__device__ __nv_bfloat16 g_wd_h[(size_t)D*FF], g_wd_l[(size_t)D*FF];
__device__ __nv_bfloat16 g_h_h[(size_t)S*D],   g_h_l[(size_t)S*D];
__device__ __nv_bfloat16 g_q_h[(size_t)S*D];
__device__ __nv_bfloat16 g_k_h[(size_t)S*D];
__device__ __nv_bfloat16 g_vt_h[(size_t)D*S];
__device__ __nv_bfloat16 g_p_h[(size_t)S*S];
__device__ __nv_bfloat16 g_av_h[(size_t)S*D],  g_av_l[(size_t)S*D];
__device__ __nv_bfloat16 g_h2_h[(size_t)S*D],  g_h2_l[(size_t)S*D];
__device__ __nv_bfloat16 g_act_h[(size_t)S*FF],g_act_l[(size_t)S*FF];
__device__ float g_qf[(size_t)S*D];
__device__ float g_kf[(size_t)S*D];
__device__ float g_vf[(size_t)S*D];
__device__ float g_sc[(size_t)S*S];
__device__ float g_x1[(size_t)S*D];
__device__ float g_gf[(size_t)S*FF];

// ------------------------- helpers ------------------------------------------
__device__ __forceinline__ uint32_t smem_u32(const void* p) {
    uint32_t a;
    asm("{ .reg .u64 t; cvta.to.shared.u64 t, %1; cvt.u32.u64 %0, t; }"
        : "=r"(a) : "l"(p));
    return a;
}

__device__ __forceinline__ void cpasync16(uint32_t dst, const void* src) {
    asm volatile("cp.async.cg.shared.global [%0], [%1], 16;"
                 :: "r"(dst), "l"(src) : "memory");
}

__device__ __forceinline__ void ldsm4(uint32_t addr, uint32_t& r0, uint32_t& r1,
                                      uint32_t& r2, uint32_t& r3) {
    asm volatile("ldmatrix.sync.aligned.m8n8.x4.shared.b16 {%0,%1,%2,%3}, [%4];"
                 : "=r"(r0), "=r"(r1), "=r"(r2), "=r"(r3) : "r"(addr));
}

__device__ __forceinline__ void mma16816(float* c, const uint32_t* a, const uint32_t* b) {
    asm volatile("mma.sync.aligned.m16n8k16.row.col.f32.bf16.bf16.f32 "
                 "{%0,%1,%2,%3}, {%4,%5,%6,%7}, {%8,%9}, {%0,%1,%2,%3};"
                 : "+f"(c[0]), "+f"(c[1]), "+f"(c[2]), "+f"(c[3])
                 : "r"(a[0]), "r"(a[1]), "r"(a[2]), "r"(a[3]),
                   "r"(b[0]), "r"(b[1]));
}

__device__ __forceinline__ void split1(float x, __nv_bfloat16* hp, __nv_bfloat16* lp) {
    __nv_bfloat16 h = __float2bfloat16(x);
    *hp = h;
    *lp = __float2bfloat16(x - __bfloat162float(h));
}

__device__ __forceinline__ void store_split2(__nv_bfloat16* oh, __nv_bfloat16* ol,
                                             size_t off, float a, float b) {
    __nv_bfloat16 ha, la, hb, lb;
    split1(a, &ha, &la);
    split1(b, &hb, &lb);
    *(uint32_t*)(oh + off) = (uint32_t)(*(uint16_t*)&ha) | ((uint32_t)(*(uint16_t*)&hb) << 16);
    *(uint32_t*)(ol + off) = (uint32_t)(*(uint16_t*)&la) | ((uint32_t)(*(uint16_t*)&lb) << 16);
}

// ------------------------- tensor-core split GEMM ----------------------------
// NPASS=3: Ah*Bh + Al*Bh + Ah*Bl. NPASS=2: (Ah+Al)*Bh = A*Bh. NPASS=1: Ah*Bh.
// OM=0: fp32 out (+res). OM=1: bf16 hi/lo split out. OM=2: silu(res)*acc, bf16 split out.
template <int OM, int NPASS>
__global__ __launch_bounds__(256, 2)
void gemm_mma(const __nv_bfloat16* __restrict__ Ah, const __nv_bfloat16* __restrict__ Al,
              const __nv_bfloat16* __restrict__ Bh, const __nv_bfloat16* __restrict__ Bl,
              float* __restrict__ C, const float* __restrict__ res,
              __nv_bfloat16* __restrict__ oh, __nv_bfloat16* __restrict__ ol,
              int M, int N, int K, float alpha)
{
    extern __shared__ __align__(128) char smem[];
    const int tid = threadIdx.x;
    const int wid = tid >> 5, lane = tid & 31;
    const int warp_m = wid & 3, warp_n = wid >> 2;
    const int bm = blockIdx.y * 128, bn = blockIdx.x * 128;
    const uint32_t sb = smem_u32(smem);
    const int nch = K / KC;

    float acc[2][8][4];
#pragma unroll
    for (int mt = 0; mt < 2; mt++)
#pragma unroll
        for (int nt = 0; nt < 8; nt++)
#pragma unroll
            for (int e = 0; e < 4; e++) acc[mt][nt][e] = 0.f;

    const int lrow = tid >> 2;
    const int lc   = tid & 3;

    auto issue = [&](int stage, int chunk) {
        const int k0 = chunk * KC;
#pragma unroll
        for (int r = 0; r < 2; r++) {
            const int row = lrow + r * 64;
            const uint32_t d = sb + stage * STGB + row * 80 + lc * 16;
            const size_t ga = (size_t)(bm + row) * K + k0 + lc * 8;
            const size_t gb = (size_t)(bn + row) * K + k0 + lc * 8;
            cpasync16(d, Ah + ga);
            if (NPASS >= 2) cpasync16(d + OPBYTES, Al + ga);
            cpasync16(d + 2 * OPBYTES, Bh + gb);
            if (NPASS == 3) cpasync16(d + 3 * OPBYTES, Bl + gb);
        }
    };

    issue(0, 0);
    asm volatile("cp.async.commit_group;" ::: "memory");

    const int quad = lane >> 3, l8 = lane & 7;
    const int a_r = (quad & 1) * 8 + l8;
    const int a_c = (quad >> 1) * 8;
    const int b_r = (quad >> 1) * 8 + l8;
    const int b_c = (quad & 1) * 8;

    for (int i = 0; i < nch; i++) {
        asm volatile("cp.async.wait_group 0;" ::: "memory");
        __syncthreads();
        if (i + 1 < nch) issue((i + 1) & (NSTAGE - 1), i + 1);
        asm volatile("cp.async.commit_group;" ::: "memory");

        const uint32_t st = sb + (i & (NSTAGE - 1)) * STGB;
#pragma unroll
        for (int ks = 0; ks < 2; ks++) {
            const int ko = ks * 16;
            uint32_t ah[2][4], al[2][4], b[8][2];
#pragma unroll
            for (int mt = 0; mt < 2; mt++) {
                const uint32_t ad = st + (warp_m * 32 + mt * 16 + a_r) * 80 + (a_c + ko) * 2;
                ldsm4(ad, ah[mt][0], ah[mt][1], ah[mt][2], ah[mt][3]);
                if (NPASS >= 2)
                    ldsm4(ad + OPBYTES, al[mt][0], al[mt][1], al[mt][2], al[mt][3]);
            }
#pragma unroll
            for (int p = 0; p < 4; p++) {
                const uint32_t bd = st + 2 * OPBYTES +
                                    (warp_n * 64 + p * 16 + b_r) * 80 + (b_c + ko) * 2;
                ldsm4(bd, b[2 * p][0], b[2 * p][1], b[2 * p + 1][0], b[2 * p + 1][1]);
            }
            // pass 1: hi*hi
#pragma unroll
            for (int mt = 0; mt < 2; mt++)
#pragma unroll
                for (int nt = 0; nt < 8; nt++) mma16816(acc[mt][nt], ah[mt], b[nt]);
            // pass 2: lo*hi
            if (NPASS >= 2) {
#pragma unroll
                for (int mt = 0; mt < 2; mt++)
#pragma unroll
                    for (int nt = 0; nt < 8; nt++) mma16816(acc[mt][nt], al[mt], b[nt]);
            }
            // pass 3: hi*lo
            if (NPASS == 3) {
#pragma unroll
                for (int p = 0; p < 4; p++) {
                    const uint32_t bd = st + 3 * OPBYTES +
                                        (warp_n * 64 + p * 16 + b_r) * 80 + (b_c + ko) * 2;
                    ldsm4(bd, b[2 * p][0], b[2 * p][1], b[2 * p + 1][0], b[2 * p + 1][1]);
                }
#pragma unroll
                for (int mt = 0; mt < 2; mt++)
#pragma unroll
                    for (int nt = 0; nt < 8; nt++) mma16816(acc[mt][nt], ah[mt], b[nt]);
            }
        }
    }

    // epilogue
    const int g2 = lane >> 2, t2 = lane & 3;
#pragma unroll
    for (int mt = 0; mt < 2; mt++) {
        const int row0 = bm + warp_m * 32 + mt * 16 + g2;
#pragma unroll
        for (int nt = 0; nt < 8; nt++) {
            const int col = bn + warp_n * 64 + nt * 8 + 2 * t2;
            float2 v0 = make_float2(acc[mt][nt][0] * alpha, acc[mt][nt][1] * alpha);
            float2 v1 = make_float2(acc[mt][nt][2] * alpha, acc[mt][nt][3] * alpha);
            if (OM == 0) {
                if (res) {
                    float2 r0 = *(const float2*)(res + (size_t)row0 * N + col);
                    float2 r1 = *(const float2*)(res + (size_t)(row0 + 8) * N + col);
                    v0.x += r0.x; v0.y += r0.y; v1.x += r1.x; v1.y += r1.y;
                }
                *(float2*)(C + (size_t)row0 * N + col) = v0;
                *(float2*)(C + (size_t)(row0 + 8) * N + col) = v1;
            } else if (OM == 1) {
                store_split2(oh, ol, (size_t)row0 * N + col, v0.x, v0.y);
                store_split2(oh, ol, (size_t)(row0 + 8) * N + col, v1.x, v1.y);
            } else {
                float2 ga = *(const float2*)(res + (size_t)row0 * N + col);
                float2 gb = *(const float2*)(res + (size_t)(row0 + 8) * N + col);
                float r0 = ga.x / (1.f + expf(-ga.x)) * v0.x;
                float r1 = ga.y / (1.f + expf(-ga.y)) * v0.y;
                float r2 = gb.x / (1.f + expf(-gb.x)) * v1.x;
                float r3 = gb.y / (1.f + expf(-gb.y)) * v1.y;
                store_split2(oh, ol, (size_t)row0 * N + col, r0, r1);
                store_split2(oh, ol, (size_t)(row0 + 8) * N + col, r2, r3);
            }
        }
    }
}

// ------------------------- elementwise kernels ------------------------------
// full hi/lo split, 16 elems/thread
__global__ __launch_bounds__(256)
void k_split(const float* __restrict__ src, __nv_bfloat16* __restrict__ h,
             __nv_bfloat16* __restrict__ l, size_t n16)
{
    size_t i = (size_t)blockIdx.x * 256 + threadIdx.x;
    if (i >= n16) return;
    float4 v[4];
#pragma unroll
    for (int j = 0; j < 4; j++) v[j] = ((const float4*)src)[4 * i + j];
    __nv_bfloat16 hv[16], lv[16];
#pragma unroll
    for (int j = 0; j < 4; j++) {
        split1(v[j].x, &hv[4 * j + 0], &lv[4 * j + 0]);
        split1(v[j].y, &hv[4 * j + 1], &lv[4 * j + 1]);
        split1(v[j].z, &hv[4 * j + 2], &lv[4 * j + 2]);
        split1(v[j].w, &hv[4 * j + 3], &lv[4 * j + 3]);
    }
    *(uint4*)(h + 16 * i)     = *(uint4*)hv;
    *(uint4*)(h + 16 * i + 8) = *(uint4*)(hv + 8);
    *(uint4*)(l + 16 * i)     = *(uint4*)lv;
    *(uint4*)(l + 16 * i + 8) = *(uint4*)(lv + 8);
}

// hi-only convert, 16 elems/thread
__global__ __launch_bounds__(256)
void k_split_hi(const float* __restrict__ src, __nv_bfloat16* __restrict__ h, size_t n16)
{
    size_t i = (size_t)blockIdx.x * 256 + threadIdx.x;
    if (i >= n16) return;
    float4 v[4];
#pragma unroll
    for (int j = 0; j < 4; j++) v[j] = ((const float4*)src)[4 * i + j];
    __nv_bfloat16 hv[16];
#pragma unroll
    for (int j = 0; j < 4; j++) {
        hv[4 * j + 0] = __float2bfloat16(v[j].x);
        hv[4 * j + 1] = __float2bfloat16(v[j].y);
        hv[4 * j + 2] = __float2bfloat16(v[j].z);
        hv[4 * j + 3] = __float2bfloat16(v[j].w);
    }
    *(uint4*)(h + 16 * i)     = *(uint4*)hv;
    *(uint4*)(h + 16 * i + 8) = *(uint4*)(hv + 8);
}

__global__ __launch_bounds__(256)
void k_rmsnorm_split(const float* __restrict__ x, const float* __restrict__ w,
                     __nv_bfloat16* __restrict__ oh, __nv_bfloat16* __restrict__ ol)
{
    const int row = blockIdx.x, tid = threadIdx.x;
    const float* xr = x + (size_t)row * D;
    float vals[8], local = 0.f;
#pragma unroll
    for (int i = 0; i < 8; i++) {
        float v = xr[tid + i * 256];
        vals[i] = v;
        local += v * v;
    }
#pragma unroll
    for (int o = 16; o > 0; o >>= 1)
        local += __shfl_xor_sync(0xffffffffu, local, o);
    __shared__ float sh[8];
    if ((tid & 31) == 0) sh[tid >> 5] = local;
    __syncthreads();
    if (tid == 0) {
        float s = 0.f;
#pragma unroll
        for (int i = 0; i < 8; i++) s += sh[i];
        sh[0] = rsqrtf(s / (float)D + EPSF);
    }
    __syncthreads();
    float scale = sh[0];
#pragma unroll
    for (int i = 0; i < 8; i++) {
        int j = tid + i * 256;
        split1(vals[i] * scale * w[j], &oh[(size_t)row * D + j], &ol[(size_t)row * D + j]);
    }
}

__global__ __launch_bounds__(256)
void k_rope_hi(const float* __restrict__ qf, const float* __restrict__ cosb,
               const float* __restrict__ sinb, __nv_bfloat16* __restrict__ oh)
{
    const int row = blockIdx.x, tid = threadIdx.x;
    const float* qr = qf + (size_t)row * D;
    const float* cr = cosb + (size_t)row * (D / 2);
    const float* sr = sinb + (size_t)row * (D / 2);
#pragma unroll
    for (int i = 0; i < 4; i++) {
        int j = tid + i * 256;
        float c = cr[j], s = sr[j];
        float x1 = qr[j], x2 = qr[j + D / 2];
        size_t o1 = (size_t)row * D + j, o2 = o1 + D / 2;
        oh[o1] = __float2bfloat16(x1 * c - x2 * s);
        oh[o2] = __float2bfloat16(x1 * s + x2 * c);
    }
}

__global__ __launch_bounds__(256)
void k_softmax_hi(const float* __restrict__ scores, __nv_bfloat16* __restrict__ ph)
{
    const int row = blockIdx.x, tid = threadIdx.x;
    const float* p = scores + (size_t)row * S;
    float vals[16], m = -1e30f;
#pragma unroll
    for (int i = 0; i < 16; i++) {
        float v = p[tid + i * 256];
        vals[i] = v;
        m = fmaxf(m, v);
    }
#pragma unroll
    for (int o = 16; o > 0; o >>= 1)
        m = fmaxf(m, __shfl_xor_sync(0xffffffffu, m, o));
    __shared__ float sh[8];
    if ((tid & 31) == 0) sh[tid >> 5] = m;
    __syncthreads();
    if (tid == 0) {
        float mm = sh[0];
#pragma unroll
        for (int i = 1; i < 8; i++) mm = fmaxf(mm, sh[i]);
        sh[0] = mm;
    }
    __syncthreads();
    m = sh[0];
    __syncthreads();
    float sum = 0.f;
#pragma unroll
    for (int i = 0; i < 16; i++) {
        vals[i] = expf(vals[i] - m);
        sum += vals[i];
    }
#pragma unroll
    for (int o = 16; o > 0; o >>= 1)
        sum += __shfl_xor_sync(0xffffffffu, sum, o);
    if ((tid & 31) == 0) sh[tid >> 5] = sum;
    __syncthreads();
    if (tid == 0) {
        float ss = 0.f;
#pragma unroll
        for (int i = 0; i < 8; i++) ss += sh[i];
        sh[0] = 1.f / ss;
    }
    __syncthreads();
    float inv = sh[0];
#pragma unroll
    for (int i = 0; i < 16; i++) {
        size_t o = (size_t)row * S + tid + i * 256;
        ph[o] = __float2bfloat16(vals[i] * inv);
    }
}

__global__ __launch_bounds__(256)
void k_transpose_hi(const float* __restrict__ v, __nv_bfloat16* __restrict__ th)
{
    __shared__ float t[32][33];
    const int d0 = blockIdx.x * 32, s0 = blockIdx.y * 32;
    const int tx = threadIdx.x & 31, ty = threadIdx.x >> 5;
#pragma unroll
    for (int j = ty; j < 32; j += 8)
        t[j][tx] = v[(size_t)(s0 + j) * D + d0 + tx];
    __syncthreads();
#pragma unroll
    for (int j = ty; j < 32; j += 8) {
        size_t o = (size_t)(d0 + j) * S + s0 + tx;
        th[o] = __float2bfloat16(t[tx][j]);
    }
}

// ------------------------- launch -------------------------------------------
static inline void split_launch(const float* src, __nv_bfloat16* h, __nv_bfloat16* l, size_t n) {
    size_t n16 = n / 16;
    k_split<<<(unsigned)((n16 + 255) / 256), 256>>>(src, h, l, n16);
}
static inline void split_hi_launch(const float* src, __nv_bfloat16* h, size_t n) {
    size_t n16 = n / 16;
    k_split_hi<<<(unsigned)((n16 + 255) / 256), 256>>>(src, h, n16);
}

extern "C" void kernel_launch(void* const* d_in, const int* in_sizes, int n_in,
                              void* d_out, int out_size)
{
    const float* x      = (const float*)d_in[0];
    const float* w_rn1  = (const float*)d_in[1];
    const float* wq     = (const float*)d_in[2];
    const float* wk     = (const float*)d_in[3];
    const float* wv     = (const float*)d_in[4];
    const float* wo     = (const float*)d_in[5];
    const float* w_rn2  = (const float*)d_in[6];
    const float* w_gate = (const float*)d_in[7];
    const float* w_up   = (const float*)d_in[8];
    const float* w_down = (const float*)d_in[9];
    const float* cosb   = (const float*)d_in[10];
    const float* sinb   = (const float*)d_in[11];
    float* out = (float*)d_out;

    static int smem_set = 0;
    if (!smem_set) {
        cudaFuncSetAttribute(gemm_mma<0,1>, cudaFuncAttributeMaxDynamicSharedMemorySize, SMEMB);
        cudaFuncSetAttribute(gemm_mma<0,2>, cudaFuncAttributeMaxDynamicSharedMemorySize, SMEMB);
        cudaFuncSetAttribute(gemm_mma<0,3>, cudaFuncAttributeMaxDynamicSharedMemorySize, SMEMB);
        cudaFuncSetAttribute(gemm_mma<1,1>, cudaFuncAttributeMaxDynamicSharedMemorySize, SMEMB);
        cudaFuncSetAttribute(gemm_mma<2,3>, cudaFuncAttributeMaxDynamicSharedMemorySize, SMEMB);
        smem_set = 1;
    }

#define SYM(p, s) do { void* _t; cudaGetSymbolAddress(&_t, s); p = (decltype(p))_t; } while (0)
    __nv_bfloat16 *wq_h, *wk_h, *wv_h, *wo_h, *wd_h, *wd_l;
    __nv_bfloat16 *wg_h, *wg_l, *wu_h, *wu_l;
    __nv_bfloat16 *h_h, *h_l, *q_h, *k_h, *vt_h, *p_h;
    __nv_bfloat16 *av_h, *av_l, *h2_h, *h2_l, *act_h, *act_l;
    float *qf, *kf, *vf, *sc, *x1, *gf;
    SYM(wq_h, g_wq_h); SYM(wk_h, g_wk_h); SYM(wv_h, g_wv_h); SYM(wo_h, g_wo_h);
    SYM(wg_h, g_wg_h); SYM(wg_l, g_wg_l); SYM(wu_h, g_wu_h); SYM(wu_l, g_wu_l);
    SYM(wd_h, g_wd_h); SYM(wd_l, g_wd_l);
    SYM(h_h, g_h_h);   SYM(h_l, g_h_l);
    SYM(q_h, g_q_h);   SYM(k_h, g_k_h);   SYM(vt_h, g_vt_h); SYM(p_h, g_p_h);
    SYM(av_h, g_av_h); SYM(av_l, g_av_l);
    SYM(h2_h, g_h2_h); SYM(h2_l, g_h2_l); SYM(act_h, g_act_h); SYM(act_l, g_act_l);
    SYM(qf, g_qf); SYM(kf, g_kf); SYM(vf, g_vf); SYM(sc, g_sc);
    SYM(x1, g_x1); SYM(gf, g_gf);
#undef SYM

    const float inv_scale = 1.f / sqrtf((float)D);

    dim3 gDD(D / 128, S / 128);
    dim3 gSS(S / 128, S / 128);
    dim3 gFFd(FF / 128, S / 128);

    // attention weight converts (hi only — 2-pass GEMMs) + first rmsnorm
    split_hi_launch(wq, wq_h, (size_t)D * D);
    split_hi_launch(wk, wk_h, (size_t)D * D);
    split_hi_launch(wv, wv_h, (size_t)D * D);
    split_hi_launch(wo, wo_h, (size_t)D * D);
    k_rmsnorm_split<<<S, 256>>>(x, w_rn1, h_h, h_l);
    // q,k,v projections (2-pass: full h x hi weights)
    gemm_mma<0,2><<<gDD, 256, SMEMB>>>(h_h, h_l, wq_h, nullptr, qf, nullptr, nullptr, nullptr, S, D, D, 1.f);
    gemm_mma<0,2><<<gDD, 256, SMEMB>>>(h_h, h_l, wk_h, nullptr, kf, nullptr, nullptr, nullptr, S, D, D, 1.f);
    gemm_mma<0,2><<<gDD, 256, SMEMB>>>(h_h, h_l, wv_h, nullptr, vf, nullptr, nullptr, nullptr, S, D, D, 1.f);
    // ffn weight splits (gate/up/down all full hi/lo — undamped paths stay eps^2)
    split_launch(w_gate, wg_h, wg_l, (size_t)FF * D);
    split_launch(w_up,   wu_h, wu_l, (size_t)FF * D);
    split_launch(w_down, wd_h, wd_l, (size_t)D * FF);
    // rope (hi only)
    k_rope_hi<<<S, 256>>>(qf, cosb, sinb, q_h);
    k_rope_hi<<<S, 256>>>(kf, cosb, sinb, k_h);
    // v transpose (hi only)
    k_transpose_hi<<<dim3(D / 32, S / 32), 256>>>(vf, vt_h);
    // scores = q @ k^T / sqrt(D)   (1-pass)
    gemm_mma<0,1><<<gSS, 256, SMEMB>>>(q_h, nullptr, k_h, nullptr, sc, nullptr, nullptr, nullptr, S, S, D, inv_scale);
    // softmax (hi only)
    k_softmax_hi<<<S, 256>>>(sc, p_h);
    // attnv = P @ V  (1-pass), epilogue writes bf16 hi/lo
    gemm_mma<1,1><<<gDD, 256, SMEMB>>>(p_h, nullptr, vt_h, nullptr, nullptr, nullptr, av_h, av_l, S, D, S, 1.f);
    // x1 = x + attnv @ wo^T  (2-pass: full attnv x hi wo)
    gemm_mma<0,2><<<gDD, 256, SMEMB>>>(av_h, av_l, wo_h, nullptr, x1, x, nullptr, nullptr, S, D, D, 1.f);
    // h2 = rmsnorm(x1)*w_rn2
    k_rmsnorm_split<<<S, 256>>>(x1, w_rn2, h2_h, h2_l);
    // gate (3-pass, fp32 out)
    gemm_mma<0,3><<<gFFd, 256, SMEMB>>>(h2_h, h2_l, wg_h, wg_l, gf, nullptr, nullptr, nullptr, S, FF, D, 1.f);
    // up (3-pass) with fused SwiGLU epilogue
    gemm_mma<2,3><<<gFFd, 256, SMEMB>>>(h2_h, h2_l, wu_h, wu_l, nullptr, gf, act_h, act_l, S, FF, D, 1.f);
    // out = x1 + act @ w_down^T  (3-pass: undamped path back to eps^2)
    gemm_mma<0,3><<<gDD, 256, SMEMB>>>(act_h, act_l, wd_h, wd_l, out, x1, nullptr, nullptr, S, D, FF, 1.f);
}

// round 15
// speedup vs baseline: 1.3688x; 1.0866x over previous
#include <cuda_runtime.h>
#include <cuda_bf16.h>
#include <stdint.h>
#include <math.h>

#define S  4096
#define D  2048
#define FF 8192
#define EPSF 1.1920929e-07f

#define KC 32                    // bf16 k per chunk
#define OPBYTES (128 * 80)       // one operand tile: 128 rows x 80B
#define STGB (4 * OPBYTES)       // Ah, Al, Bh, Bl slots
#define NSTAGE 2
#define SMEMB (NSTAGE * STGB)    // 81920 -> 2 CTAs/SM

// ------------------------- device scratch (no allocs allowed) ---------------
__device__ __nv_bfloat16 g_wq_h[(size_t)D*D];
__device__ __nv_bfloat16 g_wk_h[(size_t)D*D];
__device__ __nv_bfloat16 g_wv_h[(size_t)D*D];
__device__ __nv_bfloat16 g_wo_h[(size_t)D*D];
__device__ __nv_bfloat16 g_wg_h[(size_t)FF*D], g_wg_l[(size_t)FF*D];
__device__ __nv_bfloat16 g_wu_h[(size_t)FF*D], g_wu_l[(size_t)FF*D];
__device__ __nv_bfloat16 g_wd_h[(size_t)D*FF], g_wd_l[(size_t)D*FF];
__device__ __nv_bfloat16 g_h_h[(size_t)S*D];
__device__ __nv_bfloat16 g_q_h[(size_t)S*D];
__device__ __nv_bfloat16 g_k_h[(size_t)S*D];
__device__ __nv_bfloat16 g_vt_h[(size_t)D*S];
__device__ __nv_bfloat16 g_p_h[(size_t)S*S];
__device__ __nv_bfloat16 g_av_h[(size_t)S*D];
__device__ __nv_bfloat16 g_h2_h[(size_t)S*D],  g_h2_l[(size_t)S*D];
__device__ __nv_bfloat16 g_act_h[(size_t)S*FF],g_act_l[(size_t)S*FF];
__device__ float g_qf[(size_t)S*D];
__device__ float g_kf[(size_t)S*D];
__device__ float g_vf[(size_t)S*D];
__device__ float g_sc[(size_t)S*S];
__device__ float g_x1[(size_t)S*D];
__device__ float g_gf[(size_t)S*FF];

// ------------------------- helpers ------------------------------------------
__device__ __forceinline__ uint32_t smem_u32(const void* p) {
    uint32_t a;
    asm("{ .reg .u64 t; cvta.to.shared.u64 t, %1; cvt.u32.u64 %0, t; }"
        : "=r"(a) : "l"(p));
    return a;
}

__device__ __forceinline__ void cpasync16(uint32_t dst, const void* src) {
    asm volatile("cp.async.cg.shared.global [%0], [%1], 16;"
                 :: "r"(dst), "l"(src) : "memory");
}

__device__ __forceinline__ void ldsm4(uint32_t addr, uint32_t& r0, uint32_t& r1,
                                      uint32_t& r2, uint32_t& r3) {
    asm volatile("ldmatrix.sync.aligned.m8n8.x4.shared.b16 {%0,%1,%2,%3}, [%4];"
                 : "=r"(r0), "=r"(r1), "=r"(r2), "=r"(r3) : "r"(addr));
}

__device__ __forceinline__ void mma16816(float* c, const uint32_t* a, const uint32_t* b) {
    asm volatile("mma.sync.aligned.m16n8k16.row.col.f32.bf16.bf16.f32 "
                 "{%0,%1,%2,%3}, {%4,%5,%6,%7}, {%8,%9}, {%0,%1,%2,%3};"
                 : "+f"(c[0]), "+f"(c[1]), "+f"(c[2]), "+f"(c[3])
                 : "r"(a[0]), "r"(a[1]), "r"(a[2]), "r"(a[3]),
                   "r"(b[0]), "r"(b[1]));
}

__device__ __forceinline__ void split1(float x, __nv_bfloat16* hp, __nv_bfloat16* lp) {
    __nv_bfloat16 h = __float2bfloat16(x);
    *hp = h;
    *lp = __float2bfloat16(x - __bfloat162float(h));
}

__device__ __forceinline__ void store_split2(__nv_bfloat16* oh, __nv_bfloat16* ol,
                                             size_t off, float a, float b) {
    __nv_bfloat16 ha, la, hb, lb;
    split1(a, &ha, &la);
    split1(b, &hb, &lb);
    *(uint32_t*)(oh + off) = (uint32_t)(*(uint16_t*)&ha) | ((uint32_t)(*(uint16_t*)&hb) << 16);
    *(uint32_t*)(ol + off) = (uint32_t)(*(uint16_t*)&la) | ((uint32_t)(*(uint16_t*)&lb) << 16);
}

__device__ __forceinline__ void store_hi2(__nv_bfloat16* oh, size_t off, float a, float b) {
    __nv_bfloat16 ha = __float2bfloat16(a), hb = __float2bfloat16(b);
    *(uint32_t*)(oh + off) = (uint32_t)(*(uint16_t*)&ha) | ((uint32_t)(*(uint16_t*)&hb) << 16);
}

// ------------------------- tensor-core split GEMM ----------------------------
// NPASS=3: Ah*Bh + Al*Bh + Ah*Bl. NPASS=2: (Ah+Al)*Bh. NPASS=1: Ah*Bh.
// OM=0: fp32 out (+res). OM=1: bf16 hi/lo split out. OM=2: silu(res)*acc, bf16 split out.
// OM=3: bf16 hi-only out.
template <int OM, int NPASS>
__global__ __launch_bounds__(256, 2)
void gemm_mma(const __nv_bfloat16* __restrict__ Ah, const __nv_bfloat16* __restrict__ Al,
              const __nv_bfloat16* __restrict__ Bh, const __nv_bfloat16* __restrict__ Bl,
              float* __restrict__ C, const float* __restrict__ res,
              __nv_bfloat16* __restrict__ oh, __nv_bfloat16* __restrict__ ol,
              int M, int N, int K, float alpha)
{
    extern __shared__ __align__(128) char smem[];
    const int tid = threadIdx.x;
    const int wid = tid >> 5, lane = tid & 31;
    const int warp_m = wid & 3, warp_n = wid >> 2;
    const int bm = blockIdx.y * 128, bn = blockIdx.x * 128;
    const uint32_t sb = smem_u32(smem);
    const int nch = K / KC;

    float acc[2][8][4];
#pragma unroll
    for (int mt = 0; mt < 2; mt++)
#pragma unroll
        for (int nt = 0; nt < 8; nt++)
#pragma unroll
            for (int e = 0; e < 4; e++) acc[mt][nt][e] = 0.f;

    const int lrow = tid >> 2;
    const int lc   = tid & 3;

    auto issue = [&](int stage, int chunk) {
        const int k0 = chunk * KC;
#pragma unroll
        for (int r = 0; r < 2; r++) {
            const int row = lrow + r * 64;
            const uint32_t d = sb + stage * STGB + row * 80 + lc * 16;
            const size_t ga = (size_t)(bm + row) * K + k0 + lc * 8;
            const size_t gb = (size_t)(bn + row) * K + k0 + lc * 8;
            cpasync16(d, Ah + ga);
            if (NPASS >= 2) cpasync16(d + OPBYTES, Al + ga);
            cpasync16(d + 2 * OPBYTES, Bh + gb);
            if (NPASS == 3) cpasync16(d + 3 * OPBYTES, Bl + gb);
        }
    };

    issue(0, 0);
    asm volatile("cp.async.commit_group;" ::: "memory");

    const int quad = lane >> 3, l8 = lane & 7;
    const int a_r = (quad & 1) * 8 + l8;
    const int a_c = (quad >> 1) * 8;
    const int b_r = (quad >> 1) * 8 + l8;
    const int b_c = (quad & 1) * 8;

    for (int i = 0; i < nch; i++) {
        asm volatile("cp.async.wait_group 0;" ::: "memory");
        __syncthreads();
        if (i + 1 < nch) issue((i + 1) & (NSTAGE - 1), i + 1);
        asm volatile("cp.async.commit_group;" ::: "memory");

        const uint32_t st = sb + (i & (NSTAGE - 1)) * STGB;
#pragma unroll
        for (int ks = 0; ks < 2; ks++) {
            const int ko = ks * 16;
            uint32_t ah[2][4], al[2][4], b[8][2];
#pragma unroll
            for (int mt = 0; mt < 2; mt++) {
                const uint32_t ad = st + (warp_m * 32 + mt * 16 + a_r) * 80 + (a_c + ko) * 2;
                ldsm4(ad, ah[mt][0], ah[mt][1], ah[mt][2], ah[mt][3]);
                if (NPASS >= 2)
                    ldsm4(ad + OPBYTES, al[mt][0], al[mt][1], al[mt][2], al[mt][3]);
            }
#pragma unroll
            for (int p = 0; p < 4; p++) {
                const uint32_t bd = st + 2 * OPBYTES +
                                    (warp_n * 64 + p * 16 + b_r) * 80 + (b_c + ko) * 2;
                ldsm4(bd, b[2 * p][0], b[2 * p][1], b[2 * p + 1][0], b[2 * p + 1][1]);
            }
            // pass 1: hi*hi
#pragma unroll
            for (int mt = 0; mt < 2; mt++)
#pragma unroll
                for (int nt = 0; nt < 8; nt++) mma16816(acc[mt][nt], ah[mt], b[nt]);
            // pass 2: lo*hi
            if (NPASS >= 2) {
#pragma unroll
                for (int mt = 0; mt < 2; mt++)
#pragma unroll
                    for (int nt = 0; nt < 8; nt++) mma16816(acc[mt][nt], al[mt], b[nt]);
            }
            // pass 3: hi*lo
            if (NPASS == 3) {
#pragma unroll
                for (int p = 0; p < 4; p++) {
                    const uint32_t bd = st + 3 * OPBYTES +
                                        (warp_n * 64 + p * 16 + b_r) * 80 + (b_c + ko) * 2;
                    ldsm4(bd, b[2 * p][0], b[2 * p][1], b[2 * p + 1][0], b[2 * p + 1][1]);
                }
#pragma unroll
                for (int mt = 0; mt < 2; mt++)
#pragma unroll
                    for (int nt = 0; nt < 8; nt++) mma16816(acc[mt][nt], ah[mt], b[nt]);
            }
        }
    }

    // epilogue
    const int g2 = lane >> 2, t2 = lane & 3;
#pragma unroll
    for (int mt = 0; mt < 2; mt++) {
        const int row0 = bm + warp_m * 32 + mt * 16 + g2;
#pragma unroll
        for (int nt = 0; nt < 8; nt++) {
            const int col = bn + warp_n * 64 + nt * 8 + 2 * t2;
            float2 v0 = make_float2(acc[mt][nt][0] * alpha, acc[mt][nt][1] * alpha);
            float2 v1 = make_float2(acc[mt][nt][2] * alpha, acc[mt][nt][3] * alpha);
            if (OM == 0) {
                if (res) {
                    float2 r0 = *(const float2*)(res + (size_t)row0 * N + col);
                    float2 r1 = *(const float2*)(res + (size_t)(row0 + 8) * N + col);
                    v0.x += r0.x; v0.y += r0.y; v1.x += r1.x; v1.y += r1.y;
                }
                *(float2*)(C + (size_t)row0 * N + col) = v0;
                *(float2*)(C + (size_t)(row0 + 8) * N + col) = v1;
            } else if (OM == 1) {
                store_split2(oh, ol, (size_t)row0 * N + col, v0.x, v0.y);
                store_split2(oh, ol, (size_t)(row0 + 8) * N + col, v1.x, v1.y);
            } else if (OM == 2) {
                float2 ga = *(const float2*)(res + (size_t)row0 * N + col);
                float2 gb = *(const float2*)(res + (size_t)(row0 + 8) * N + col);
                float r0 = ga.x / (1.f + expf(-ga.x)) * v0.x;
                float r1 = ga.y / (1.f + expf(-ga.y)) * v0.y;
                float r2 = gb.x / (1.f + expf(-gb.x)) * v1.x;
                float r3 = gb.y / (1.f + expf(-gb.y)) * v1.y;
                store_split2(oh, ol, (size_t)row0 * N + col, r0, r1);
                store_split2(oh, ol, (size_t)(row0 + 8) * N + col, r2, r3);
            } else {
                store_hi2(oh, (size_t)row0 * N + col, v0.x, v0.y);
                store_hi2(oh, (size_t)(row0 + 8) * N + col, v1.x, v1.y);
            }
        }
    }
}

// ------------------------- elementwise kernels ------------------------------
// full hi/lo split, 16 elems/thread
__global__ __launch_bounds__(256)
void k_split(const float* __restrict__ src, __nv_bfloat16* __restrict__ h,
             __nv_bfloat16* __restrict__ l, size_t n16)
{
    size_t i = (size_t)blockIdx.x * 256 + threadIdx.x;
    if (i >= n16) return;
    float4 v[4];
#pragma unroll
    for (int j = 0; j < 4; j++) v[j] = ((const float4*)src)[4 * i + j];
    __nv_bfloat16 hv[16], lv[16];
#pragma unroll
    for (int j = 0; j < 4; j++) {
        split1(v[j].x, &hv[4 * j + 0], &lv[4 * j + 0]);
        split1(v[j].y, &hv[4 * j + 1], &lv[4 * j + 1]);
        split1(v[j].z, &hv[4 * j + 2], &lv[4 * j + 2]);
        split1(v[j].w, &hv[4 * j + 3], &lv[4 * j + 3]);
    }
    *(uint4*)(h + 16 * i)     = *(uint4*)hv;
    *(uint4*)(h + 16 * i + 8) = *(uint4*)(hv + 8);
    *(uint4*)(l + 16 * i)     = *(uint4*)lv;
    *(uint4*)(l + 16 * i + 8) = *(uint4*)(lv + 8);
}

// hi-only convert, 16 elems/thread
__global__ __launch_bounds__(256)
void k_split_hi(const float* __restrict__ src, __nv_bfloat16* __restrict__ h, size_t n16)
{
    size_t i = (size_t)blockIdx.x * 256 + threadIdx.x;
    if (i >= n16) return;
    float4 v[4];
#pragma unroll
    for (int j = 0; j < 4; j++) v[j] = ((const float4*)src)[4 * i + j];
    __nv_bfloat16 hv[16];
#pragma unroll
    for (int j = 0; j < 4; j++) {
        hv[4 * j + 0] = __float2bfloat16(v[j].x);
        hv[4 * j + 1] = __float2bfloat16(v[j].y);
        hv[4 * j + 2] = __float2bfloat16(v[j].z);
        hv[4 * j + 3] = __float2bfloat16(v[j].w);
    }
    *(uint4*)(h + 16 * i)     = *(uint4*)hv;
    *(uint4*)(h + 16 * i + 8) = *(uint4*)(hv + 8);
}

__global__ __launch_bounds__(256)
void k_rmsnorm_split(const float* __restrict__ x, const float* __restrict__ w,
                     __nv_bfloat16* __restrict__ oh, __nv_bfloat16* __restrict__ ol)
{
    const int row = blockIdx.x, tid = threadIdx.x;
    const float* xr = x + (size_t)row * D;
    float vals[8], local = 0.f;
#pragma unroll
    for (int i = 0; i < 8; i++) {
        float v = xr[tid + i * 256];
        vals[i] = v;
        local += v * v;
    }
#pragma unroll
    for (int o = 16; o > 0; o >>= 1)
        local += __shfl_xor_sync(0xffffffffu, local, o);
    __shared__ float sh[8];
    if ((tid & 31) == 0) sh[tid >> 5] = local;
    __syncthreads();
    if (tid == 0) {
        float s = 0.f;
#pragma unroll
        for (int i = 0; i < 8; i++) s += sh[i];
        sh[0] = rsqrtf(s / (float)D + EPSF);
    }
    __syncthreads();
    float scale = sh[0];
#pragma unroll
    for (int i = 0; i < 8; i++) {
        int j = tid + i * 256;
        split1(vals[i] * scale * w[j], &oh[(size_t)row * D + j], &ol[(size_t)row * D + j]);
    }
}

__global__ __launch_bounds__(256)
void k_rmsnorm_hi(const float* __restrict__ x, const float* __restrict__ w,
                  __nv_bfloat16* __restrict__ oh)
{
    const int row = blockIdx.x, tid = threadIdx.x;
    const float* xr = x + (size_t)row * D;
    float vals[8], local = 0.f;
#pragma unroll
    for (int i = 0; i < 8; i++) {
        float v = xr[tid + i * 256];
        vals[i] = v;
        local += v * v;
    }
#pragma unroll
    for (int o = 16; o > 0; o >>= 1)
        local += __shfl_xor_sync(0xffffffffu, local, o);
    __shared__ float sh[8];
    if ((tid & 31) == 0) sh[tid >> 5] = local;
    __syncthreads();
    if (tid == 0) {
        float s = 0.f;
#pragma unroll
        for (int i = 0; i < 8; i++) s += sh[i];
        sh[0] = rsqrtf(s / (float)D + EPSF);
    }
    __syncthreads();
    float scale = sh[0];
#pragma unroll
    for (int i = 0; i < 8; i++) {
        int j = tid + i * 256;
        oh[(size_t)row * D + j] = __float2bfloat16(vals[i] * scale * w[j]);
    }
}

__global__ __launch_bounds__(256)
void k_rope_hi(const float* __restrict__ qf, const float* __restrict__ cosb,
               const float* __restrict__ sinb, __nv_bfloat16* __restrict__ oh)
{
    const int row = blockIdx.x, tid = threadIdx.x;
    const float* qr = qf + (size_t)row * D;
    const float* cr = cosb + (size_t)row * (D / 2);
    const float* sr = sinb + (size_t)row * (D / 2);
#pragma unroll
    for (int i = 0; i < 4; i++) {
        int j = tid + i * 256;
        float c = cr[j], s = sr[j];
        float x1 = qr[j], x2 = qr[j + D / 2];
        size_t o1 = (size_t)row * D + j, o2 = o1 + D / 2;
        oh[o1] = __float2bfloat16(x1 * c - x2 * s);
        oh[o2] = __float2bfloat16(x1 * s + x2 * c);
    }
}

__global__ __launch_bounds__(256)
void k_softmax_hi(const float* __restrict__ scores, __nv_bfloat16* __restrict__ ph)
{
    const int row = blockIdx.x, tid = threadIdx.x;
    const float* p = scores + (size_t)row * S;
    float vals[16], m = -1e30f;
#pragma unroll
    for (int i = 0; i < 16; i++) {
        float v = p[tid + i * 256];
        vals[i] = v;
        m = fmaxf(m, v);
    }
#pragma unroll
    for (int o = 16; o > 0; o >>= 1)
        m = fmaxf(m, __shfl_xor_sync(0xffffffffu, m, o));
    __shared__ float sh[8];
    if ((tid & 31) == 0) sh[tid >> 5] = m;
    __syncthreads();
    if (tid == 0) {
        float mm = sh[0];
#pragma unroll
        for (int i = 1; i < 8; i++) mm = fmaxf(mm, sh[i]);
        sh[0] = mm;
    }
    __syncthreads();
    m = sh[0];
    __syncthreads();
    float sum = 0.f;
#pragma unroll
    for (int i = 0; i < 16; i++) {
        vals[i] = expf(vals[i] - m);
        sum += vals[i];
    }
#pragma unroll
    for (int o = 16; o > 0; o >>= 1)
        sum += __shfl_xor_sync(0xffffffffu, sum, o);
    if ((tid & 31) == 0) sh[tid >> 5] = sum;
    __syncthreads();
    if (tid == 0) {
        float ss = 0.f;
#pragma unroll
        for (int i = 0; i < 8; i++) ss += sh[i];
        sh[0] = 1.f / ss;
    }
    __syncthreads();
    float inv = sh[0];
#pragma unroll
    for (int i = 0; i < 16; i++) {
        size_t o = (size_t)row * S + tid + i * 256;
        ph[o] = __float2bfloat16(vals[i] * inv);
    }
}

__global__ __launch_bounds__(256)
void k_transpose_hi(const float* __restrict__ v, __nv_bfloat16* __restrict__ th)
{
    __shared__ float t[32][33];
    const int d0 = blockIdx.x * 32, s0 = blockIdx.y * 32;
    const int tx = threadIdx.x & 31, ty = threadIdx.x >> 5;
#pragma unroll
    for (int j = ty; j < 32; j += 8)
        t[j][tx] = v[(size_t)(s0 + j) * D + d0 + tx];
    __syncthreads();
#pragma unroll
    for (int j = ty; j < 32; j += 8) {
        size_t o = (size_t)(d0 + j) * S + s0 + tx;
        th[o] = __float2bfloat16(t[tx][j]);
    }
}

// ------------------------- launch -------------------------------------------
static inline void split_launch(const float* src, __nv_bfloat16* h, __nv_bfloat16* l, size_t n) {
    size_t n16 = n / 16;
    k_split<<<(unsigned)((n16 + 255) / 256), 256>>>(src, h, l, n16);
}
static inline void split_hi_launch(const float* src, __nv_bfloat16* h, size_t n) {
    size_t n16 = n / 16;
    k_split_hi<<<(unsigned)((n16 + 255) / 256), 256>>>(src, h, n16);
}

extern "C" void kernel_launch(void* const* d_in, const int* in_sizes, int n_in,
                              void* d_out, int out_size)
{
    const float* x      = (const float*)d_in[0];
    const float* w_rn1  = (const float*)d_in[1];
    const float* wq     = (const float*)d_in[2];
    const float* wk     = (const float*)d_in[3];
    const float* wv     = (const float*)d_in[4];
    const float* wo     = (const float*)d_in[5];
    const float* w_rn2  = (const float*)d_in[6];
    const float* w_gate = (const float*)d_in[7];
    const float* w_up   = (const float*)d_in[8];
    const float* w_down = (const float*)d_in[9];
    const float* cosb   = (const float*)d_in[10];
    const float* sinb   = (const float*)d_in[11];
    float* out = (float*)d_out;

    static int smem_set = 0;
    if (!smem_set) {
        cudaFuncSetAttribute(gemm_mma<0,1>, cudaFuncAttributeMaxDynamicSharedMemorySize, SMEMB);
        cudaFuncSetAttribute(gemm_mma<0,3>, cudaFuncAttributeMaxDynamicSharedMemorySize, SMEMB);
        cudaFuncSetAttribute(gemm_mma<3,1>, cudaFuncAttributeMaxDynamicSharedMemorySize, SMEMB);
        cudaFuncSetAttribute(gemm_mma<2,3>, cudaFuncAttributeMaxDynamicSharedMemorySize, SMEMB);
        smem_set = 1;
    }

#define SYM(p, s) do { void* _t; cudaGetSymbolAddress(&_t, s); p = (decltype(p))_t; } while (0)
    __nv_bfloat16 *wq_h, *wk_h, *wv_h, *wo_h, *wd_h, *wd_l;
    __nv_bfloat16 *wg_h, *wg_l, *wu_h, *wu_l;
    __nv_bfloat16 *h_h, *q_h, *k_h, *vt_h, *p_h, *av_h;
    __nv_bfloat16 *h2_h, *h2_l, *act_h, *act_l;
    float *qf, *kf, *vf, *sc, *x1, *gf;
    SYM(wq_h, g_wq_h); SYM(wk_h, g_wk_h); SYM(wv_h, g_wv_h); SYM(wo_h, g_wo_h);
    SYM(wg_h, g_wg_h); SYM(wg_l, g_wg_l); SYM(wu_h, g_wu_h); SYM(wu_l, g_wu_l);
    SYM(wd_h, g_wd_h); SYM(wd_l, g_wd_l);
    SYM(h_h, g_h_h);
    SYM(q_h, g_q_h);   SYM(k_h, g_k_h);   SYM(vt_h, g_vt_h); SYM(p_h, g_p_h);
    SYM(av_h, g_av_h);
    SYM(h2_h, g_h2_h); SYM(h2_l, g_h2_l); SYM(act_h, g_act_h); SYM(act_l, g_act_l);
    SYM(qf, g_qf); SYM(kf, g_kf); SYM(vf, g_vf); SYM(sc, g_sc);
    SYM(x1, g_x1); SYM(gf, g_gf);
#undef SYM

    const float inv_scale = 1.f / sqrtf((float)D);

    dim3 gDD(D / 128, S / 128);
    dim3 gSS(S / 128, S / 128);
    dim3 gFFd(FF / 128, S / 128);

    // attention weight converts (hi only) + first rmsnorm (hi only)
    split_hi_launch(wq, wq_h, (size_t)D * D);
    split_hi_launch(wk, wk_h, (size_t)D * D);
    split_hi_launch(wv, wv_h, (size_t)D * D);
    split_hi_launch(wo, wo_h, (size_t)D * D);
    k_rmsnorm_hi<<<S, 256>>>(x, w_rn1, h_h);
    // q,k,v projections (1-pass: h hi x w hi — result truncated to bf16 anyway)
    gemm_mma<0,1><<<gDD, 256, SMEMB>>>(h_h, nullptr, wq_h, nullptr, qf, nullptr, nullptr, nullptr, S, D, D, 1.f);
    gemm_mma<0,1><<<gDD, 256, SMEMB>>>(h_h, nullptr, wk_h, nullptr, kf, nullptr, nullptr, nullptr, S, D, D, 1.f);
    gemm_mma<0,1><<<gDD, 256, SMEMB>>>(h_h, nullptr, wv_h, nullptr, vf, nullptr, nullptr, nullptr, S, D, D, 1.f);
    // ffn weight splits (gate/up/down all full hi/lo — undamped paths stay eps^2)
    split_launch(w_gate, wg_h, wg_l, (size_t)FF * D);
    split_launch(w_up,   wu_h, wu_l, (size_t)FF * D);
    split_launch(w_down, wd_h, wd_l, (size_t)D * FF);
    // rope (hi only)
    k_rope_hi<<<S, 256>>>(qf, cosb, sinb, q_h);
    k_rope_hi<<<S, 256>>>(kf, cosb, sinb, k_h);
    // v transpose (hi only)
    k_transpose_hi<<<dim3(D / 32, S / 32), 256>>>(vf, vt_h);
    // scores = q @ k^T / sqrt(D)   (1-pass)
    gemm_mma<0,1><<<gSS, 256, SMEMB>>>(q_h, nullptr, k_h, nullptr, sc, nullptr, nullptr, nullptr, S, S, D, inv_scale);
    // softmax (hi only)
    k_softmax_hi<<<S, 256>>>(sc, p_h);
    // attnv = P @ V  (1-pass), epilogue writes bf16 hi only
    gemm_mma<3,1><<<gDD, 256, SMEMB>>>(p_h, nullptr, vt_h, nullptr, nullptr, nullptr, av_h, nullptr, S, D, S, 1.f);
    // x1 = x + attnv @ wo^T  (1-pass: attnv branch is ~70x smaller than x)
    gemm_mma<0,1><<<gDD, 256, SMEMB>>>(av_h, nullptr, wo_h, nullptr, x1, x, nullptr, nullptr, S, D, D, 1.f);
    // h2 = rmsnorm(x1)*w_rn2 (full split — feeds undamped FFN)
    k_rmsnorm_split<<<S, 256>>>(x1, w_rn2, h2_h, h2_l);
    // gate (3-pass, fp32 out)
    gemm_mma<0,3><<<gFFd, 256, SMEMB>>>(h2_h, h2_l, wg_h, wg_l, gf, nullptr, nullptr, nullptr, S, FF, D, 1.f);
    // up (3-pass) with fused SwiGLU epilogue
    gemm_mma<2,3><<<gFFd, 256, SMEMB>>>(h2_h, h2_l, wu_h, wu_l, nullptr, gf, act_h, act_l, S, FF, D, 1.f);
    // out = x1 + act @ w_down^T  (3-pass)
    gemm_mma<0,3><<<gDD, 256, SMEMB>>>(act_h, act_l, wd_h, wd_l, out, x1, nullptr, nullptr, S, D, FF, 1.f);
}

// round 16
// speedup vs baseline: 1.3767x; 1.0057x over previous
#include <cuda_runtime.h>
#include <cuda_bf16.h>
#include <stdint.h>
#include <math.h>

#define S  4096
#define D  2048
#define FF 8192
#define EPSF 1.1920929e-07f

#define KC 32                    // bf16 k per chunk
#define OPBYTES (128 * 80)       // one operand tile: 128 rows x 80B
#define STGB (4 * OPBYTES)       // Ah, Al, Bh, Bl slots
#define NSTAGE 2
#define SMEMB (NSTAGE * STGB)    // 81920 -> 2 CTAs/SM

// ------------------------- device scratch (no allocs allowed) ---------------
__device__ __nv_bfloat16 g_wq_h[(size_t)D*D];
__device__ __nv_bfloat16 g_wk_h[(size_t)D*D];
__device__ __nv_bfloat16 g_wv_h[(size_t)D*D];
__device__ __nv_bfloat16 g_wo_h[(size_t)D*D];
__device__ __nv_bfloat16 g_wg_h[(size_t)FF*D], g_wg_l[(size_t)FF*D];
__device__ __nv_bfloat16 g_wu_h[(size_t)FF*D], g_wu_l[(size_t)FF*D];
__device__ __nv_bfloat16 g_wd_h[(size_t)D*FF], g_wd_l[(size_t)D*FF];
__device__ __nv_bfloat16 g_h_h[(size_t)S*D];
__device__ __nv_bfloat16 g_q_h[(size_t)S*D];
__device__ __nv_bfloat16 g_k_h[(size_t)S*D];
__device__ __nv_bfloat16 g_vt_h[(size_t)D*S];
__device__ __nv_bfloat16 g_p_h[(size_t)S*S];
__device__ __nv_bfloat16 g_av_h[(size_t)S*D];
__device__ __nv_bfloat16 g_h2_h[(size_t)S*D],  g_h2_l[(size_t)S*D];
__device__ __nv_bfloat16 g_act_h[(size_t)S*FF],g_act_l[(size_t)S*FF];
__device__ float g_qf[(size_t)S*D];
__device__ float g_kf[(size_t)S*D];
__device__ float g_vf[(size_t)S*D];
__device__ float g_sc[(size_t)S*S];
__device__ float g_x1[(size_t)S*D];
__device__ float g_gf[(size_t)S*FF];

// ------------------------- helpers ------------------------------------------
__device__ __forceinline__ uint32_t smem_u32(const void* p) {
    uint32_t a;
    asm("{ .reg .u64 t; cvta.to.shared.u64 t, %1; cvt.u32.u64 %0, t; }"
        : "=r"(a) : "l"(p));
    return a;
}

__device__ __forceinline__ void cpasync16(uint32_t dst, const void* src) {
    asm volatile("cp.async.cg.shared.global [%0], [%1], 16;"
                 :: "r"(dst), "l"(src) : "memory");
}

__device__ __forceinline__ void ldsm4(uint32_t addr, uint32_t& r0, uint32_t& r1,
                                      uint32_t& r2, uint32_t& r3) {
    asm volatile("ldmatrix.sync.aligned.m8n8.x4.shared.b16 {%0,%1,%2,%3}, [%4];"
                 : "=r"(r0), "=r"(r1), "=r"(r2), "=r"(r3) : "r"(addr));
}

__device__ __forceinline__ void mma16816(float* c, const uint32_t* a, const uint32_t* b) {
    asm volatile("mma.sync.aligned.m16n8k16.row.col.f32.bf16.bf16.f32 "
                 "{%0,%1,%2,%3}, {%4,%5,%6,%7}, {%8,%9}, {%0,%1,%2,%3};"
                 : "+f"(c[0]), "+f"(c[1]), "+f"(c[2]), "+f"(c[3])
                 : "r"(a[0]), "r"(a[1]), "r"(a[2]), "r"(a[3]),
                   "r"(b[0]), "r"(b[1]));
}

__device__ __forceinline__ void split1(float x, __nv_bfloat16* hp, __nv_bfloat16* lp) {
    __nv_bfloat16 h = __float2bfloat16(x);
    *hp = h;
    *lp = __float2bfloat16(x - __bfloat162float(h));
}

__device__ __forceinline__ void store_split2(__nv_bfloat16* oh, __nv_bfloat16* ol,
                                             size_t off, float a, float b) {
    __nv_bfloat16 ha, la, hb, lb;
    split1(a, &ha, &la);
    split1(b, &hb, &lb);
    *(uint32_t*)(oh + off) = (uint32_t)(*(uint16_t*)&ha) | ((uint32_t)(*(uint16_t*)&hb) << 16);
    *(uint32_t*)(ol + off) = (uint32_t)(*(uint16_t*)&la) | ((uint32_t)(*(uint16_t*)&lb) << 16);
}

__device__ __forceinline__ void store_hi2(__nv_bfloat16* oh, size_t off, float a, float b) {
    __nv_bfloat16 ha = __float2bfloat16(a), hb = __float2bfloat16(b);
    *(uint32_t*)(oh + off) = (uint32_t)(*(uint16_t*)&ha) | ((uint32_t)(*(uint16_t*)&hb) << 16);
}

// ------------------------- tensor-core split GEMM ----------------------------
// NPASS=3: Ah*Bh + Al*Bh + Ah*Bl. NPASS=2: (Ah+Al)*Bh. NPASS=1: Ah*Bh.
// OM=0: fp32 out (+res). OM=1: bf16 hi/lo split out. OM=2: silu(res)*acc, bf16 split out.
// OM=3: bf16 hi-only out.
template <int OM, int NPASS>
__global__ __launch_bounds__(256, 2)
void gemm_mma(const __nv_bfloat16* __restrict__ Ah, const __nv_bfloat16* __restrict__ Al,
              const __nv_bfloat16* __restrict__ Bh, const __nv_bfloat16* __restrict__ Bl,
              float* __restrict__ C, const float* __restrict__ res,
              __nv_bfloat16* __restrict__ oh, __nv_bfloat16* __restrict__ ol,
              int M, int N, int K, float alpha)
{
    extern __shared__ __align__(128) char smem[];
    const int tid = threadIdx.x;
    const int wid = tid >> 5, lane = tid & 31;
    const int warp_m = wid & 3, warp_n = wid >> 2;
    const int bm = blockIdx.y * 128, bn = blockIdx.x * 128;
    const uint32_t sb = smem_u32(smem);
    const int nch = K / KC;

    float acc[2][8][4];
#pragma unroll
    for (int mt = 0; mt < 2; mt++)
#pragma unroll
        for (int nt = 0; nt < 8; nt++)
#pragma unroll
            for (int e = 0; e < 4; e++) acc[mt][nt][e] = 0.f;

    const int lrow = tid >> 2;
    const int lc   = tid & 3;

    auto issue = [&](int stage, int chunk) {
        const int k0 = chunk * KC;
#pragma unroll
        for (int r = 0; r < 2; r++) {
            const int row = lrow + r * 64;
            const uint32_t d = sb + stage * STGB + row * 80 + lc * 16;
            const size_t ga = (size_t)(bm + row) * K + k0 + lc * 8;
            const size_t gb = (size_t)(bn + row) * K + k0 + lc * 8;
            cpasync16(d, Ah + ga);
            if (NPASS >= 2) cpasync16(d + OPBYTES, Al + ga);
            cpasync16(d + 2 * OPBYTES, Bh + gb);
            if (NPASS == 3) cpasync16(d + 3 * OPBYTES, Bl + gb);
        }
    };

    issue(0, 0);
    asm volatile("cp.async.commit_group;" ::: "memory");

    const int quad = lane >> 3, l8 = lane & 7;
    const int a_r = (quad & 1) * 8 + l8;
    const int a_c = (quad >> 1) * 8;
    const int b_r = (quad >> 1) * 8 + l8;
    const int b_c = (quad & 1) * 8;

    for (int i = 0; i < nch; i++) {
        asm volatile("cp.async.wait_group 0;" ::: "memory");
        __syncthreads();
        if (i + 1 < nch) issue((i + 1) & (NSTAGE - 1), i + 1);
        asm volatile("cp.async.commit_group;" ::: "memory");

        const uint32_t st = sb + (i & (NSTAGE - 1)) * STGB;
#pragma unroll
        for (int ks = 0; ks < 2; ks++) {
            const int ko = ks * 16;
            uint32_t ah[2][4], al[2][4], b[8][2];
#pragma unroll
            for (int mt = 0; mt < 2; mt++) {
                const uint32_t ad = st + (warp_m * 32 + mt * 16 + a_r) * 80 + (a_c + ko) * 2;
                ldsm4(ad, ah[mt][0], ah[mt][1], ah[mt][2], ah[mt][3]);
                if (NPASS >= 2)
                    ldsm4(ad + OPBYTES, al[mt][0], al[mt][1], al[mt][2], al[mt][3]);
            }
#pragma unroll
            for (int p = 0; p < 4; p++) {
                const uint32_t bd = st + 2 * OPBYTES +
                                    (warp_n * 64 + p * 16 + b_r) * 80 + (b_c + ko) * 2;
                ldsm4(bd, b[2 * p][0], b[2 * p][1], b[2 * p + 1][0], b[2 * p + 1][1]);
            }
            // pass 1: hi*hi
#pragma unroll
            for (int mt = 0; mt < 2; mt++)
#pragma unroll
                for (int nt = 0; nt < 8; nt++) mma16816(acc[mt][nt], ah[mt], b[nt]);
            // pass 2: lo*hi
            if (NPASS >= 2) {
#pragma unroll
                for (int mt = 0; mt < 2; mt++)
#pragma unroll
                    for (int nt = 0; nt < 8; nt++) mma16816(acc[mt][nt], al[mt], b[nt]);
            }
            // pass 3: hi*lo
            if (NPASS == 3) {
#pragma unroll
                for (int p = 0; p < 4; p++) {
                    const uint32_t bd = st + 3 * OPBYTES +
                                        (warp_n * 64 + p * 16 + b_r) * 80 + (b_c + ko) * 2;
                    ldsm4(bd, b[2 * p][0], b[2 * p][1], b[2 * p + 1][0], b[2 * p + 1][1]);
                }
#pragma unroll
                for (int mt = 0; mt < 2; mt++)
#pragma unroll
                    for (int nt = 0; nt < 8; nt++) mma16816(acc[mt][nt], ah[mt], b[nt]);
            }
        }
    }

    // epilogue
    const int g2 = lane >> 2, t2 = lane & 3;
#pragma unroll
    for (int mt = 0; mt < 2; mt++) {
        const int row0 = bm + warp_m * 32 + mt * 16 + g2;
#pragma unroll
        for (int nt = 0; nt < 8; nt++) {
            const int col = bn + warp_n * 64 + nt * 8 + 2 * t2;
            float2 v0 = make_float2(acc[mt][nt][0] * alpha, acc[mt][nt][1] * alpha);
            float2 v1 = make_float2(acc[mt][nt][2] * alpha, acc[mt][nt][3] * alpha);
            if (OM == 0) {
                if (res) {
                    float2 r0 = *(const float2*)(res + (size_t)row0 * N + col);
                    float2 r1 = *(const float2*)(res + (size_t)(row0 + 8) * N + col);
                    v0.x += r0.x; v0.y += r0.y; v1.x += r1.x; v1.y += r1.y;
                }
                *(float2*)(C + (size_t)row0 * N + col) = v0;
                *(float2*)(C + (size_t)(row0 + 8) * N + col) = v1;
            } else if (OM == 1) {
                store_split2(oh, ol, (size_t)row0 * N + col, v0.x, v0.y);
                store_split2(oh, ol, (size_t)(row0 + 8) * N + col, v1.x, v1.y);
            } else if (OM == 2) {
                float2 ga = *(const float2*)(res + (size_t)row0 * N + col);
                float2 gb = *(const float2*)(res + (size_t)(row0 + 8) * N + col);
                float r0 = ga.x / (1.f + expf(-ga.x)) * v0.x;
                float r1 = ga.y / (1.f + expf(-ga.y)) * v0.y;
                float r2 = gb.x / (1.f + expf(-gb.x)) * v1.x;
                float r3 = gb.y / (1.f + expf(-gb.y)) * v1.y;
                store_split2(oh, ol, (size_t)row0 * N + col, r0, r1);
                store_split2(oh, ol, (size_t)(row0 + 8) * N + col, r2, r3);
            } else {
                store_hi2(oh, (size_t)row0 * N + col, v0.x, v0.y);
                store_hi2(oh, (size_t)(row0 + 8) * N + col, v1.x, v1.y);
            }
        }
    }
}

// ------------------------- elementwise kernels ------------------------------
// full hi/lo split, 16 elems/thread
__global__ __launch_bounds__(256)
void k_split(const float* __restrict__ src, __nv_bfloat16* __restrict__ h,
             __nv_bfloat16* __restrict__ l, size_t n16)
{
    size_t i = (size_t)blockIdx.x * 256 + threadIdx.x;
    if (i >= n16) return;
    float4 v[4];
#pragma unroll
    for (int j = 0; j < 4; j++) v[j] = ((const float4*)src)[4 * i + j];
    __nv_bfloat16 hv[16], lv[16];
#pragma unroll
    for (int j = 0; j < 4; j++) {
        split1(v[j].x, &hv[4 * j + 0], &lv[4 * j + 0]);
        split1(v[j].y, &hv[4 * j + 1], &lv[4 * j + 1]);
        split1(v[j].z, &hv[4 * j + 2], &lv[4 * j + 2]);
        split1(v[j].w, &hv[4 * j + 3], &lv[4 * j + 3]);
    }
    *(uint4*)(h + 16 * i)     = *(uint4*)hv;
    *(uint4*)(h + 16 * i + 8) = *(uint4*)(hv + 8);
    *(uint4*)(l + 16 * i)     = *(uint4*)lv;
    *(uint4*)(l + 16 * i + 8) = *(uint4*)(lv + 8);
}

// hi-only convert, 16 elems/thread
__global__ __launch_bounds__(256)
void k_split_hi(const float* __restrict__ src, __nv_bfloat16* __restrict__ h, size_t n16)
{
    size_t i = (size_t)blockIdx.x * 256 + threadIdx.x;
    if (i >= n16) return;
    float4 v[4];
#pragma unroll
    for (int j = 0; j < 4; j++) v[j] = ((const float4*)src)[4 * i + j];
    __nv_bfloat16 hv[16];
#pragma unroll
    for (int j = 0; j < 4; j++) {
        hv[4 * j + 0] = __float2bfloat16(v[j].x);
        hv[4 * j + 1] = __float2bfloat16(v[j].y);
        hv[4 * j + 2] = __float2bfloat16(v[j].z);
        hv[4 * j + 3] = __float2bfloat16(v[j].w);
    }
    *(uint4*)(h + 16 * i)     = *(uint4*)hv;
    *(uint4*)(h + 16 * i + 8) = *(uint4*)(hv + 8);
}

__global__ __launch_bounds__(256)
void k_rmsnorm_split(const float* __restrict__ x, const float* __restrict__ w,
                     __nv_bfloat16* __restrict__ oh, __nv_bfloat16* __restrict__ ol)
{
    const int row = blockIdx.x, tid = threadIdx.x;
    const float* xr = x + (size_t)row * D;
    float vals[8], local = 0.f;
#pragma unroll
    for (int i = 0; i < 8; i++) {
        float v = xr[tid + i * 256];
        vals[i] = v;
        local += v * v;
    }
#pragma unroll
    for (int o = 16; o > 0; o >>= 1)
        local += __shfl_xor_sync(0xffffffffu, local, o);
    __shared__ float sh[8];
    if ((tid & 31) == 0) sh[tid >> 5] = local;
    __syncthreads();
    if (tid == 0) {
        float s = 0.f;
#pragma unroll
        for (int i = 0; i < 8; i++) s += sh[i];
        sh[0] = rsqrtf(s / (float)D + EPSF);
    }
    __syncthreads();
    float scale = sh[0];
#pragma unroll
    for (int i = 0; i < 8; i++) {
        int j = tid + i * 256;
        split1(vals[i] * scale * w[j], &oh[(size_t)row * D + j], &ol[(size_t)row * D + j]);
    }
}

__global__ __launch_bounds__(256)
void k_rmsnorm_hi(const float* __restrict__ x, const float* __restrict__ w,
                  __nv_bfloat16* __restrict__ oh)
{
    const int row = blockIdx.x, tid = threadIdx.x;
    const float* xr = x + (size_t)row * D;
    float vals[8], local = 0.f;
#pragma unroll
    for (int i = 0; i < 8; i++) {
        float v = xr[tid + i * 256];
        vals[i] = v;
        local += v * v;
    }
#pragma unroll
    for (int o = 16; o > 0; o >>= 1)
        local += __shfl_xor_sync(0xffffffffu, local, o);
    __shared__ float sh[8];
    if ((tid & 31) == 0) sh[tid >> 5] = local;
    __syncthreads();
    if (tid == 0) {
        float s = 0.f;
#pragma unroll
        for (int i = 0; i < 8; i++) s += sh[i];
        sh[0] = rsqrtf(s / (float)D + EPSF);
    }
    __syncthreads();
    float scale = sh[0];
#pragma unroll
    for (int i = 0; i < 8; i++) {
        int j = tid + i * 256;
        oh[(size_t)row * D + j] = __float2bfloat16(vals[i] * scale * w[j]);
    }
}

__global__ __launch_bounds__(256)
void k_rope_hi(const float* __restrict__ qf, const float* __restrict__ cosb,
               const float* __restrict__ sinb, __nv_bfloat16* __restrict__ oh)
{
    const int row = blockIdx.x, tid = threadIdx.x;
    const float* qr = qf + (size_t)row * D;
    const float* cr = cosb + (size_t)row * (D / 2);
    const float* sr = sinb + (size_t)row * (D / 2);
#pragma unroll
    for (int i = 0; i < 4; i++) {
        int j = tid + i * 256;
        float c = cr[j], s = sr[j];
        float x1 = qr[j], x2 = qr[j + D / 2];
        size_t o1 = (size_t)row * D + j, o2 = o1 + D / 2;
        oh[o1] = __float2bfloat16(x1 * c - x2 * s);
        oh[o2] = __float2bfloat16(x1 * s + x2 * c);
    }
}

__global__ __launch_bounds__(256)
void k_softmax_hi(const float* __restrict__ scores, __nv_bfloat16* __restrict__ ph)
{
    const int row = blockIdx.x, tid = threadIdx.x;
    const float* p = scores + (size_t)row * S;
    float vals[16], m = -1e30f;
#pragma unroll
    for (int i = 0; i < 16; i++) {
        float v = p[tid + i * 256];
        vals[i] = v;
        m = fmaxf(m, v);
    }
#pragma unroll
    for (int o = 16; o > 0; o >>= 1)
        m = fmaxf(m, __shfl_xor_sync(0xffffffffu, m, o));
    __shared__ float sh[8];
    if ((tid & 31) == 0) sh[tid >> 5] = m;
    __syncthreads();
    if (tid == 0) {
        float mm = sh[0];
#pragma unroll
        for (int i = 1; i < 8; i++) mm = fmaxf(mm, sh[i]);
        sh[0] = mm;
    }
    __syncthreads();
    m = sh[0];
    __syncthreads();
    float sum = 0.f;
#pragma unroll
    for (int i = 0; i < 16; i++) {
        vals[i] = expf(vals[i] - m);
        sum += vals[i];
    }
#pragma unroll
    for (int o = 16; o > 0; o >>= 1)
        sum += __shfl_xor_sync(0xffffffffu, sum, o);
    if ((tid & 31) == 0) sh[tid >> 5] = sum;
    __syncthreads();
    if (tid == 0) {
        float ss = 0.f;
#pragma unroll
        for (int i = 0; i < 8; i++) ss += sh[i];
        sh[0] = 1.f / ss;
    }
    __syncthreads();
    float inv = sh[0];
#pragma unroll
    for (int i = 0; i < 16; i++) {
        size_t o = (size_t)row * S + tid + i * 256;
        ph[o] = __float2bfloat16(vals[i] * inv);
    }
}

__global__ __launch_bounds__(256)
void k_transpose_hi(const float* __restrict__ v, __nv_bfloat16* __restrict__ th)
{
    __shared__ float t[32][33];
    const int d0 = blockIdx.x * 32, s0 = blockIdx.y * 32;
    const int tx = threadIdx.x & 31, ty = threadIdx.x >> 5;
#pragma unroll
    for (int j = ty; j < 32; j += 8)
        t[j][tx] = v[(size_t)(s0 + j) * D + d0 + tx];
    __syncthreads();
#pragma unroll
    for (int j = ty; j < 32; j += 8) {
        size_t o = (size_t)(d0 + j) * S + s0 + tx;
        th[o] = __float2bfloat16(t[tx][j]);
    }
}

// ------------------------- launch -------------------------------------------
static inline void split_launch_s(cudaStream_t st, const float* src,
                                  __nv_bfloat16* h, __nv_bfloat16* l, size_t n) {
    size_t n16 = n / 16;
    k_split<<<(unsigned)((n16 + 255) / 256), 256, 0, st>>>(src, h, l, n16);
}
static inline void split_hi_launch_s(cudaStream_t st, const float* src,
                                     __nv_bfloat16* h, size_t n) {
    size_t n16 = n / 16;
    k_split_hi<<<(unsigned)((n16 + 255) / 256), 256, 0, st>>>(src, h, n16);
}

extern "C" void kernel_launch(void* const* d_in, const int* in_sizes, int n_in,
                              void* d_out, int out_size)
{
    const float* x      = (const float*)d_in[0];
    const float* w_rn1  = (const float*)d_in[1];
    const float* wq     = (const float*)d_in[2];
    const float* wk     = (const float*)d_in[3];
    const float* wv     = (const float*)d_in[4];
    const float* wo     = (const float*)d_in[5];
    const float* w_rn2  = (const float*)d_in[6];
    const float* w_gate = (const float*)d_in[7];
    const float* w_up   = (const float*)d_in[8];
    const float* w_down = (const float*)d_in[9];
    const float* cosb   = (const float*)d_in[10];
    const float* sinb   = (const float*)d_in[11];
    float* out = (float*)d_out;

    static int init_done = 0;
    static cudaStream_t s1;
    static cudaEvent_t ev_fork, ev_att, ev_ffn;
    if (!init_done) {
        cudaFuncSetAttribute(gemm_mma<0,1>, cudaFuncAttributeMaxDynamicSharedMemorySize, SMEMB);
        cudaFuncSetAttribute(gemm_mma<0,3>, cudaFuncAttributeMaxDynamicSharedMemorySize, SMEMB);
        cudaFuncSetAttribute(gemm_mma<3,1>, cudaFuncAttributeMaxDynamicSharedMemorySize, SMEMB);
        cudaFuncSetAttribute(gemm_mma<2,3>, cudaFuncAttributeMaxDynamicSharedMemorySize, SMEMB);
        cudaStreamCreateWithFlags(&s1, cudaStreamNonBlocking);
        cudaEventCreateWithFlags(&ev_fork, cudaEventDisableTiming);
        cudaEventCreateWithFlags(&ev_att,  cudaEventDisableTiming);
        cudaEventCreateWithFlags(&ev_ffn,  cudaEventDisableTiming);
        init_done = 1;
    }

#define SYM(p, s) do { void* _t; cudaGetSymbolAddress(&_t, s); p = (decltype(p))_t; } while (0)
    __nv_bfloat16 *wq_h, *wk_h, *wv_h, *wo_h, *wd_h, *wd_l;
    __nv_bfloat16 *wg_h, *wg_l, *wu_h, *wu_l;
    __nv_bfloat16 *h_h, *q_h, *k_h, *vt_h, *p_h, *av_h;
    __nv_bfloat16 *h2_h, *h2_l, *act_h, *act_l;
    float *qf, *kf, *vf, *sc, *x1, *gf;
    SYM(wq_h, g_wq_h); SYM(wk_h, g_wk_h); SYM(wv_h, g_wv_h); SYM(wo_h, g_wo_h);
    SYM(wg_h, g_wg_h); SYM(wg_l, g_wg_l); SYM(wu_h, g_wu_h); SYM(wu_l, g_wu_l);
    SYM(wd_h, g_wd_h); SYM(wd_l, g_wd_l);
    SYM(h_h, g_h_h);
    SYM(q_h, g_q_h);   SYM(k_h, g_k_h);   SYM(vt_h, g_vt_h); SYM(p_h, g_p_h);
    SYM(av_h, g_av_h);
    SYM(h2_h, g_h2_h); SYM(h2_l, g_h2_l); SYM(act_h, g_act_h); SYM(act_l, g_act_l);
    SYM(qf, g_qf); SYM(kf, g_kf); SYM(vf, g_vf); SYM(sc, g_sc);
    SYM(x1, g_x1); SYM(gf, g_gf);
#undef SYM

    const float inv_scale = 1.f / sqrtf((float)D);

    dim3 gDD(D / 128, S / 128);
    dim3 gSS(S / 128, S / 128);
    dim3 gFFd(FF / 128, S / 128);

    // ---- fork: weight converts on side stream s1 ----------------------------
    cudaEventRecord(ev_fork, 0);
    cudaStreamWaitEvent(s1, ev_fork, 0);
    split_hi_launch_s(s1, wq, wq_h, (size_t)D * D);
    split_hi_launch_s(s1, wk, wk_h, (size_t)D * D);
    split_hi_launch_s(s1, wv, wv_h, (size_t)D * D);
    split_hi_launch_s(s1, wo, wo_h, (size_t)D * D);
    cudaEventRecord(ev_att, s1);
    split_launch_s(s1, w_gate, wg_h, wg_l, (size_t)FF * D);
    split_launch_s(s1, w_up,   wu_h, wu_l, (size_t)FF * D);
    split_launch_s(s1, w_down, wd_h, wd_l, (size_t)D * FF);
    cudaEventRecord(ev_ffn, s1);

    // ---- main stream: compute ----------------------------------------------
    k_rmsnorm_hi<<<S, 256>>>(x, w_rn1, h_h);
    cudaStreamWaitEvent(0, ev_att, 0);   // need wq/wk/wv/wo converts
    // q,k,v projections (1-pass)
    gemm_mma<0,1><<<gDD, 256, SMEMB>>>(h_h, nullptr, wq_h, nullptr, qf, nullptr, nullptr, nullptr, S, D, D, 1.f);
    gemm_mma<0,1><<<gDD, 256, SMEMB>>>(h_h, nullptr, wk_h, nullptr, kf, nullptr, nullptr, nullptr, S, D, D, 1.f);
    gemm_mma<0,1><<<gDD, 256, SMEMB>>>(h_h, nullptr, wv_h, nullptr, vf, nullptr, nullptr, nullptr, S, D, D, 1.f);
    // rope (hi only)
    k_rope_hi<<<S, 256>>>(qf, cosb, sinb, q_h);
    k_rope_hi<<<S, 256>>>(kf, cosb, sinb, k_h);
    // v transpose (hi only)
    k_transpose_hi<<<dim3(D / 32, S / 32), 256>>>(vf, vt_h);
    // scores = q @ k^T / sqrt(D)   (1-pass)
    gemm_mma<0,1><<<gSS, 256, SMEMB>>>(q_h, nullptr, k_h, nullptr, sc, nullptr, nullptr, nullptr, S, S, D, inv_scale);
    // softmax (hi only)
    k_softmax_hi<<<S, 256>>>(sc, p_h);
    // attnv = P @ V  (1-pass), epilogue writes bf16 hi only
    gemm_mma<3,1><<<gDD, 256, SMEMB>>>(p_h, nullptr, vt_h, nullptr, nullptr, nullptr, av_h, nullptr, S, D, S, 1.f);
    // x1 = x + attnv @ wo^T  (1-pass)
    gemm_mma<0,1><<<gDD, 256, SMEMB>>>(av_h, nullptr, wo_h, nullptr, x1, x, nullptr, nullptr, S, D, D, 1.f);
    // h2 = rmsnorm(x1)*w_rn2 (full split — feeds undamped FFN)
    k_rmsnorm_split<<<S, 256>>>(x1, w_rn2, h2_h, h2_l);
    cudaStreamWaitEvent(0, ev_ffn, 0);   // join: FFN weight converts done
    // gate (3-pass, fp32 out)
    gemm_mma<0,3><<<gFFd, 256, SMEMB>>>(h2_h, h2_l, wg_h, wg_l, gf, nullptr, nullptr, nullptr, S, FF, D, 1.f);
    // up (3-pass) with fused SwiGLU epilogue
    gemm_mma<2,3><<<gFFd, 256, SMEMB>>>(h2_h, h2_l, wu_h, wu_l, nullptr, gf, act_h, act_l, S, FF, D, 1.f);
    // out = x1 + act @ w_down^T  (3-pass)
    gemm_mma<0,3><<<gDD, 256, SMEMB>>>(act_h, act_l, wd_h, wd_l, out, x1, nullptr, nullptr, S, D, FF, 1.f);
}

// round 17
// speedup vs baseline: 1.3920x; 1.0111x over previous
#include <cuda_runtime.h>
#include <cuda_bf16.h>
#include <stdint.h>
#include <math.h>

#define S  4096
#define D  2048
#define FF 8192
#define EPSF 1.1920929e-07f

#define KC 32                    // bf16 k per chunk
#define OPBYTES (128 * 80)       // one operand tile: 128 rows x 80B
#define STGB (4 * OPBYTES)       // Ah, Al, Bh, Bl slots
#define NSTAGE 2
#define SMEMB (NSTAGE * STGB)    // 81920 -> 2 CTAs/SM

// ------------------------- device scratch (no allocs allowed) ---------------
__device__ __nv_bfloat16 g_wqkv_h[(size_t)3*D*D];   // wq | wk | wv concatenated
__device__ __nv_bfloat16 g_wo_h[(size_t)D*D];
__device__ __nv_bfloat16 g_wg_h[(size_t)FF*D], g_wg_l[(size_t)FF*D];
__device__ __nv_bfloat16 g_wu_h[(size_t)FF*D], g_wu_l[(size_t)FF*D];
__device__ __nv_bfloat16 g_wd_h[(size_t)D*FF], g_wd_l[(size_t)D*FF];
__device__ __nv_bfloat16 g_h_h[(size_t)S*D];
__device__ __nv_bfloat16 g_q_h[(size_t)S*D];
__device__ __nv_bfloat16 g_k_h[(size_t)S*D];
__device__ __nv_bfloat16 g_vt_h[(size_t)D*S];
__device__ __nv_bfloat16 g_p_h[(size_t)S*S];
__device__ __nv_bfloat16 g_av_h[(size_t)S*D];
__device__ __nv_bfloat16 g_h2_h[(size_t)S*D],  g_h2_l[(size_t)S*D];
__device__ __nv_bfloat16 g_act_h[(size_t)S*FF],g_act_l[(size_t)S*FF];
__device__ float g_qkvf[(size_t)S*3*D];
__device__ float g_x1[(size_t)S*D];
__device__ float g_gf[(size_t)S*FF];

// ------------------------- helpers ------------------------------------------
__device__ __forceinline__ uint32_t smem_u32(const void* p) {
    uint32_t a;
    asm("{ .reg .u64 t; cvta.to.shared.u64 t, %1; cvt.u32.u64 %0, t; }"
        : "=r"(a) : "l"(p));
    return a;
}

__device__ __forceinline__ void cpasync16(uint32_t dst, const void* src) {
    asm volatile("cp.async.cg.shared.global [%0], [%1], 16;"
                 :: "r"(dst), "l"(src) : "memory");
}

__device__ __forceinline__ void ldsm4(uint32_t addr, uint32_t& r0, uint32_t& r1,
                                      uint32_t& r2, uint32_t& r3) {
    asm volatile("ldmatrix.sync.aligned.m8n8.x4.shared.b16 {%0,%1,%2,%3}, [%4];"
                 : "=r"(r0), "=r"(r1), "=r"(r2), "=r"(r3) : "r"(addr));
}

__device__ __forceinline__ void mma16816(float* c, const uint32_t* a, const uint32_t* b) {
    asm volatile("mma.sync.aligned.m16n8k16.row.col.f32.bf16.bf16.f32 "
                 "{%0,%1,%2,%3}, {%4,%5,%6,%7}, {%8,%9}, {%0,%1,%2,%3};"
                 : "+f"(c[0]), "+f"(c[1]), "+f"(c[2]), "+f"(c[3])
                 : "r"(a[0]), "r"(a[1]), "r"(a[2]), "r"(a[3]),
                   "r"(b[0]), "r"(b[1]));
}

__device__ __forceinline__ void split1(float x, __nv_bfloat16* hp, __nv_bfloat16* lp) {
    __nv_bfloat16 h = __float2bfloat16(x);
    *hp = h;
    *lp = __float2bfloat16(x - __bfloat162float(h));
}

__device__ __forceinline__ void store_split2(__nv_bfloat16* oh, __nv_bfloat16* ol,
                                             size_t off, float a, float b) {
    __nv_bfloat16 ha, la, hb, lb;
    split1(a, &ha, &la);
    split1(b, &hb, &lb);
    *(uint32_t*)(oh + off) = (uint32_t)(*(uint16_t*)&ha) | ((uint32_t)(*(uint16_t*)&hb) << 16);
    *(uint32_t*)(ol + off) = (uint32_t)(*(uint16_t*)&la) | ((uint32_t)(*(uint16_t*)&lb) << 16);
}

__device__ __forceinline__ void store_hi2(__nv_bfloat16* oh, size_t off, float a, float b) {
    __nv_bfloat16 ha = __float2bfloat16(a), hb = __float2bfloat16(b);
    *(uint32_t*)(oh + off) = (uint32_t)(*(uint16_t*)&ha) | ((uint32_t)(*(uint16_t*)&hb) << 16);
}

// ------------------------- tensor-core split GEMM ----------------------------
// NPASS=3: Ah*Bh + Al*Bh + Ah*Bl. NPASS=2: (Ah+Al)*Bh. NPASS=1: Ah*Bh.
// OM=0: fp32 out (+res). OM=1: bf16 hi/lo split out. OM=2: silu(res)*acc, bf16 split out.
// OM=3: bf16 hi-only out.
template <int OM, int NPASS>
__global__ __launch_bounds__(256, 2)
void gemm_mma(const __nv_bfloat16* __restrict__ Ah, const __nv_bfloat16* __restrict__ Al,
              const __nv_bfloat16* __restrict__ Bh, const __nv_bfloat16* __restrict__ Bl,
              float* __restrict__ C, const float* __restrict__ res,
              __nv_bfloat16* __restrict__ oh, __nv_bfloat16* __restrict__ ol,
              int M, int N, int K, float alpha)
{
    extern __shared__ __align__(128) char smem[];
    const int tid = threadIdx.x;
    const int wid = tid >> 5, lane = tid & 31;
    const int warp_m = wid & 3, warp_n = wid >> 2;
    const int bm = blockIdx.y * 128, bn = blockIdx.x * 128;
    const uint32_t sb = smem_u32(smem);
    const int nch = K / KC;

    float acc[2][8][4];
#pragma unroll
    for (int mt = 0; mt < 2; mt++)
#pragma unroll
        for (int nt = 0; nt < 8; nt++)
#pragma unroll
            for (int e = 0; e < 4; e++) acc[mt][nt][e] = 0.f;

    const int lrow = tid >> 2;
    const int lc   = tid & 3;

    auto issue = [&](int stage, int chunk) {
        const int k0 = chunk * KC;
#pragma unroll
        for (int r = 0; r < 2; r++) {
            const int row = lrow + r * 64;
            const uint32_t d = sb + stage * STGB + row * 80 + lc * 16;
            const size_t ga = (size_t)(bm + row) * K + k0 + lc * 8;
            const size_t gb = (size_t)(bn + row) * K + k0 + lc * 8;
            cpasync16(d, Ah + ga);
            if (NPASS >= 2) cpasync16(d + OPBYTES, Al + ga);
            cpasync16(d + 2 * OPBYTES, Bh + gb);
            if (NPASS == 3) cpasync16(d + 3 * OPBYTES, Bl + gb);
        }
    };

    issue(0, 0);
    asm volatile("cp.async.commit_group;" ::: "memory");

    const int quad = lane >> 3, l8 = lane & 7;
    const int a_r = (quad & 1) * 8 + l8;
    const int a_c = (quad >> 1) * 8;
    const int b_r = (quad >> 1) * 8 + l8;
    const int b_c = (quad & 1) * 8;

    for (int i = 0; i < nch; i++) {
        asm volatile("cp.async.wait_group 0;" ::: "memory");
        __syncthreads();
        if (i + 1 < nch) issue((i + 1) & (NSTAGE - 1), i + 1);
        asm volatile("cp.async.commit_group;" ::: "memory");

        const uint32_t st = sb + (i & (NSTAGE - 1)) * STGB;
#pragma unroll
        for (int ks = 0; ks < 2; ks++) {
            const int ko = ks * 16;
            uint32_t ah[2][4], al[2][4], b[8][2];
#pragma unroll
            for (int mt = 0; mt < 2; mt++) {
                const uint32_t ad = st + (warp_m * 32 + mt * 16 + a_r) * 80 + (a_c + ko) * 2;
                ldsm4(ad, ah[mt][0], ah[mt][1], ah[mt][2], ah[mt][3]);
                if (NPASS >= 2)
                    ldsm4(ad + OPBYTES, al[mt][0], al[mt][1], al[mt][2], al[mt][3]);
            }
#pragma unroll
            for (int p = 0; p < 4; p++) {
                const uint32_t bd = st + 2 * OPBYTES +
                                    (warp_n * 64 + p * 16 + b_r) * 80 + (b_c + ko) * 2;
                ldsm4(bd, b[2 * p][0], b[2 * p][1], b[2 * p + 1][0], b[2 * p + 1][1]);
            }
            // pass 1: hi*hi
#pragma unroll
            for (int mt = 0; mt < 2; mt++)
#pragma unroll
                for (int nt = 0; nt < 8; nt++) mma16816(acc[mt][nt], ah[mt], b[nt]);
            // pass 2: lo*hi
            if (NPASS >= 2) {
#pragma unroll
                for (int mt = 0; mt < 2; mt++)
#pragma unroll
                    for (int nt = 0; nt < 8; nt++) mma16816(acc[mt][nt], al[mt], b[nt]);
            }
            // pass 3: hi*lo
            if (NPASS == 3) {
#pragma unroll
                for (int p = 0; p < 4; p++) {
                    const uint32_t bd = st + 3 * OPBYTES +
                                        (warp_n * 64 + p * 16 + b_r) * 80 + (b_c + ko) * 2;
                    ldsm4(bd, b[2 * p][0], b[2 * p][1], b[2 * p + 1][0], b[2 * p + 1][1]);
                }
#pragma unroll
                for (int mt = 0; mt < 2; mt++)
#pragma unroll
                    for (int nt = 0; nt < 8; nt++) mma16816(acc[mt][nt], ah[mt], b[nt]);
            }
        }
    }

    // epilogue
    const int g2 = lane >> 2, t2 = lane & 3;
#pragma unroll
    for (int mt = 0; mt < 2; mt++) {
        const int row0 = bm + warp_m * 32 + mt * 16 + g2;
#pragma unroll
        for (int nt = 0; nt < 8; nt++) {
            const int col = bn + warp_n * 64 + nt * 8 + 2 * t2;
            float2 v0 = make_float2(acc[mt][nt][0] * alpha, acc[mt][nt][1] * alpha);
            float2 v1 = make_float2(acc[mt][nt][2] * alpha, acc[mt][nt][3] * alpha);
            if (OM == 0) {
                if (res) {
                    float2 r0 = *(const float2*)(res + (size_t)row0 * N + col);
                    float2 r1 = *(const float2*)(res + (size_t)(row0 + 8) * N + col);
                    v0.x += r0.x; v0.y += r0.y; v1.x += r1.x; v1.y += r1.y;
                }
                *(float2*)(C + (size_t)row0 * N + col) = v0;
                *(float2*)(C + (size_t)(row0 + 8) * N + col) = v1;
            } else if (OM == 1) {
                store_split2(oh, ol, (size_t)row0 * N + col, v0.x, v0.y);
                store_split2(oh, ol, (size_t)(row0 + 8) * N + col, v1.x, v1.y);
            } else if (OM == 2) {
                float2 ga = *(const float2*)(res + (size_t)row0 * N + col);
                float2 gb = *(const float2*)(res + (size_t)(row0 + 8) * N + col);
                float r0 = ga.x / (1.f + expf(-ga.x)) * v0.x;
                float r1 = ga.y / (1.f + expf(-ga.y)) * v0.y;
                float r2 = gb.x / (1.f + expf(-gb.x)) * v1.x;
                float r3 = gb.y / (1.f + expf(-gb.y)) * v1.y;
                store_split2(oh, ol, (size_t)row0 * N + col, r0, r1);
                store_split2(oh, ol, (size_t)(row0 + 8) * N + col, r2, r3);
            } else {
                store_hi2(oh, (size_t)row0 * N + col, v0.x, v0.y);
                store_hi2(oh, (size_t)(row0 + 8) * N + col, v1.x, v1.y);
            }
        }
    }
}

// ------------------------- elementwise kernels ------------------------------
__global__ __launch_bounds__(256)
void k_split(const float* __restrict__ src, __nv_bfloat16* __restrict__ h,
             __nv_bfloat16* __restrict__ l, size_t n16)
{
    size_t i = (size_t)blockIdx.x * 256 + threadIdx.x;
    if (i >= n16) return;
    float4 v[4];
#pragma unroll
    for (int j = 0; j < 4; j++) v[j] = ((const float4*)src)[4 * i + j];
    __nv_bfloat16 hv[16], lv[16];
#pragma unroll
    for (int j = 0; j < 4; j++) {
        split1(v[j].x, &hv[4 * j + 0], &lv[4 * j + 0]);
        split1(v[j].y, &hv[4 * j + 1], &lv[4 * j + 1]);
        split1(v[j].z, &hv[4 * j + 2], &lv[4 * j + 2]);
        split1(v[j].w, &hv[4 * j + 3], &lv[4 * j + 3]);
    }
    *(uint4*)(h + 16 * i)     = *(uint4*)hv;
    *(uint4*)(h + 16 * i + 8) = *(uint4*)(hv + 8);
    *(uint4*)(l + 16 * i)     = *(uint4*)lv;
    *(uint4*)(l + 16 * i + 8) = *(uint4*)(lv + 8);
}

__global__ __launch_bounds__(256)
void k_split_hi(const float* __restrict__ src, __nv_bfloat16* __restrict__ h, size_t n16)
{
    size_t i = (size_t)blockIdx.x * 256 + threadIdx.x;
    if (i >= n16) return;
    float4 v[4];
#pragma unroll
    for (int j = 0; j < 4; j++) v[j] = ((const float4*)src)[4 * i + j];
    __nv_bfloat16 hv[16];
#pragma unroll
    for (int j = 0; j < 4; j++) {
        hv[4 * j + 0] = __float2bfloat16(v[j].x);
        hv[4 * j + 1] = __float2bfloat16(v[j].y);
        hv[4 * j + 2] = __float2bfloat16(v[j].z);
        hv[4 * j + 3] = __float2bfloat16(v[j].w);
    }
    *(uint4*)(h + 16 * i)     = *(uint4*)hv;
    *(uint4*)(h + 16 * i + 8) = *(uint4*)(hv + 8);
}

__global__ __launch_bounds__(256)
void k_rmsnorm_split(const float* __restrict__ x, const float* __restrict__ w,
                     __nv_bfloat16* __restrict__ oh, __nv_bfloat16* __restrict__ ol)
{
    const int row = blockIdx.x, tid = threadIdx.x;
    const float* xr = x + (size_t)row * D;
    float vals[8], local = 0.f;
#pragma unroll
    for (int i = 0; i < 8; i++) {
        float v = xr[tid + i * 256];
        vals[i] = v;
        local += v * v;
    }
#pragma unroll
    for (int o = 16; o > 0; o >>= 1)
        local += __shfl_xor_sync(0xffffffffu, local, o);
    __shared__ float sh[8];
    if ((tid & 31) == 0) sh[tid >> 5] = local;
    __syncthreads();
    if (tid == 0) {
        float s = 0.f;
#pragma unroll
        for (int i = 0; i < 8; i++) s += sh[i];
        sh[0] = rsqrtf(s / (float)D + EPSF);
    }
    __syncthreads();
    float scale = sh[0];
#pragma unroll
    for (int i = 0; i < 8; i++) {
        int j = tid + i * 256;
        split1(vals[i] * scale * w[j], &oh[(size_t)row * D + j], &ol[(size_t)row * D + j]);
    }
}

__global__ __launch_bounds__(256)
void k_rmsnorm_hi(const float* __restrict__ x, const float* __restrict__ w,
                  __nv_bfloat16* __restrict__ oh)
{
    const int row = blockIdx.x, tid = threadIdx.x;
    const float* xr = x + (size_t)row * D;
    float vals[8], local = 0.f;
#pragma unroll
    for (int i = 0; i < 8; i++) {
        float v = xr[tid + i * 256];
        vals[i] = v;
        local += v * v;
    }
#pragma unroll
    for (int o = 16; o > 0; o >>= 1)
        local += __shfl_xor_sync(0xffffffffu, local, o);
    __shared__ float sh[8];
    if ((tid & 31) == 0) sh[tid >> 5] = local;
    __syncthreads();
    if (tid == 0) {
        float s = 0.f;
#pragma unroll
        for (int i = 0; i < 8; i++) s += sh[i];
        sh[0] = rsqrtf(s / (float)D + EPSF);
    }
    __syncthreads();
    float scale = sh[0];
#pragma unroll
    for (int i = 0; i < 8; i++) {
        int j = tid + i * 256;
        oh[(size_t)row * D + j] = __float2bfloat16(vals[i] * scale * w[j]);
    }
}

// rope with leading-dim (source rows of width ld; q/k at column offset baked into ptr)
__global__ __launch_bounds__(256)
void k_rope_hi(const float* __restrict__ qf, int ld, const float* __restrict__ cosb,
               const float* __restrict__ sinb, __nv_bfloat16* __restrict__ oh)
{
    const int row = blockIdx.x, tid = threadIdx.x;
    const float* qr = qf + (size_t)row * ld;
    const float* cr = cosb + (size_t)row * (D / 2);
    const float* sr = sinb + (size_t)row * (D / 2);
#pragma unroll
    for (int i = 0; i < 4; i++) {
        int j = tid + i * 256;
        float c = cr[j], s = sr[j];
        float x1 = qr[j], x2 = qr[j + D / 2];
        size_t o1 = (size_t)row * D + j, o2 = o1 + D / 2;
        oh[o1] = __float2bfloat16(x1 * c - x2 * s);
        oh[o2] = __float2bfloat16(x1 * s + x2 * c);
    }
}

// in-place bf16 softmax over S columns
__global__ __launch_bounds__(256)
void k_softmax_bf(__nv_bfloat16* __restrict__ p)
{
    const int row = blockIdx.x, tid = threadIdx.x;
    __nv_bfloat16* pr = p + (size_t)row * S;
    float vals[16], m = -1e30f;
#pragma unroll
    for (int i = 0; i < 16; i++) {
        float v = __bfloat162float(pr[tid + i * 256]);
        vals[i] = v;
        m = fmaxf(m, v);
    }
#pragma unroll
    for (int o = 16; o > 0; o >>= 1)
        m = fmaxf(m, __shfl_xor_sync(0xffffffffu, m, o));
    __shared__ float sh[8];
    if ((tid & 31) == 0) sh[tid >> 5] = m;
    __syncthreads();
    if (tid == 0) {
        float mm = sh[0];
#pragma unroll
        for (int i = 1; i < 8; i++) mm = fmaxf(mm, sh[i]);
        sh[0] = mm;
    }
    __syncthreads();
    m = sh[0];
    __syncthreads();
    float sum = 0.f;
#pragma unroll
    for (int i = 0; i < 16; i++) {
        vals[i] = expf(vals[i] - m);
        sum += vals[i];
    }
#pragma unroll
    for (int o = 16; o > 0; o >>= 1)
        sum += __shfl_xor_sync(0xffffffffu, sum, o);
    if ((tid & 31) == 0) sh[tid >> 5] = sum;
    __syncthreads();
    if (tid == 0) {
        float ss = 0.f;
#pragma unroll
        for (int i = 0; i < 8; i++) ss += sh[i];
        sh[0] = 1.f / ss;
    }
    __syncthreads();
    float inv = sh[0];
#pragma unroll
    for (int i = 0; i < 16; i++)
        pr[tid + i * 256] = __float2bfloat16(vals[i] * inv);
}

// transpose with leading-dim (v column block baked into ptr)
__global__ __launch_bounds__(256)
void k_transpose_hi(const float* __restrict__ v, int ld, __nv_bfloat16* __restrict__ th)
{
    __shared__ float t[32][33];
    const int d0 = blockIdx.x * 32, s0 = blockIdx.y * 32;
    const int tx = threadIdx.x & 31, ty = threadIdx.x >> 5;
#pragma unroll
    for (int j = ty; j < 32; j += 8)
        t[j][tx] = v[(size_t)(s0 + j) * ld + d0 + tx];
    __syncthreads();
#pragma unroll
    for (int j = ty; j < 32; j += 8) {
        size_t o = (size_t)(d0 + j) * S + s0 + tx;
        th[o] = __float2bfloat16(t[tx][j]);
    }
}

// ------------------------- launch -------------------------------------------
static inline void split_launch_s(cudaStream_t st, const float* src,
                                  __nv_bfloat16* h, __nv_bfloat16* l, size_t n) {
    size_t n16 = n / 16;
    k_split<<<(unsigned)((n16 + 255) / 256), 256, 0, st>>>(src, h, l, n16);
}
static inline void split_hi_launch_s(cudaStream_t st, const float* src,
                                     __nv_bfloat16* h, size_t n) {
    size_t n16 = n / 16;
    k_split_hi<<<(unsigned)((n16 + 255) / 256), 256, 0, st>>>(src, h, n16);
}

extern "C" void kernel_launch(void* const* d_in, const int* in_sizes, int n_in,
                              void* d_out, int out_size)
{
    const float* x      = (const float*)d_in[0];
    const float* w_rn1  = (const float*)d_in[1];
    const float* wq     = (const float*)d_in[2];
    const float* wk     = (const float*)d_in[3];
    const float* wv     = (const float*)d_in[4];
    const float* wo     = (const float*)d_in[5];
    const float* w_rn2  = (const float*)d_in[6];
    const float* w_gate = (const float*)d_in[7];
    const float* w_up   = (const float*)d_in[8];
    const float* w_down = (const float*)d_in[9];
    const float* cosb   = (const float*)d_in[10];
    const float* sinb   = (const float*)d_in[11];
    float* out = (float*)d_out;

    static int init_done = 0;
    static cudaStream_t s1;
    static cudaEvent_t ev_fork, ev_att, ev_ffn;
    if (!init_done) {
        cudaFuncSetAttribute(gemm_mma<0,1>, cudaFuncAttributeMaxDynamicSharedMemorySize, SMEMB);
        cudaFuncSetAttribute(gemm_mma<0,3>, cudaFuncAttributeMaxDynamicSharedMemorySize, SMEMB);
        cudaFuncSetAttribute(gemm_mma<3,1>, cudaFuncAttributeMaxDynamicSharedMemorySize, SMEMB);
        cudaFuncSetAttribute(gemm_mma<2,3>, cudaFuncAttributeMaxDynamicSharedMemorySize, SMEMB);
        cudaStreamCreateWithFlags(&s1, cudaStreamNonBlocking);
        cudaEventCreateWithFlags(&ev_fork, cudaEventDisableTiming);
        cudaEventCreateWithFlags(&ev_att,  cudaEventDisableTiming);
        cudaEventCreateWithFlags(&ev_ffn,  cudaEventDisableTiming);
        init_done = 1;
    }

#define SYM(p, s) do { void* _t; cudaGetSymbolAddress(&_t, s); p = (decltype(p))_t; } while (0)
    __nv_bfloat16 *wqkv_h, *wo_h, *wd_h, *wd_l;
    __nv_bfloat16 *wg_h, *wg_l, *wu_h, *wu_l;
    __nv_bfloat16 *h_h, *q_h, *k_h, *vt_h, *p_h, *av_h;
    __nv_bfloat16 *h2_h, *h2_l, *act_h, *act_l;
    float *qkvf, *x1, *gf;
    SYM(wqkv_h, g_wqkv_h); SYM(wo_h, g_wo_h);
    SYM(wg_h, g_wg_h); SYM(wg_l, g_wg_l); SYM(wu_h, g_wu_h); SYM(wu_l, g_wu_l);
    SYM(wd_h, g_wd_h); SYM(wd_l, g_wd_l);
    SYM(h_h, g_h_h);
    SYM(q_h, g_q_h);   SYM(k_h, g_k_h);   SYM(vt_h, g_vt_h); SYM(p_h, g_p_h);
    SYM(av_h, g_av_h);
    SYM(h2_h, g_h2_h); SYM(h2_l, g_h2_l); SYM(act_h, g_act_h); SYM(act_l, g_act_l);
    SYM(qkvf, g_qkvf); SYM(x1, g_x1); SYM(gf, g_gf);
#undef SYM

    const float inv_scale = 1.f / sqrtf((float)D);

    dim3 gQKV(3 * D / 128, S / 128);   // merged QKV: N = 6144
    dim3 gDD(D / 128, S / 128);
    dim3 gSS(S / 128, S / 128);
    dim3 gFFd(FF / 128, S / 128);

    // ---- fork: weight converts on side stream s1 ----------------------------
    cudaEventRecord(ev_fork, 0);
    cudaStreamWaitEvent(s1, ev_fork, 0);
    split_hi_launch_s(s1, wq, wqkv_h,                      (size_t)D * D);
    split_hi_launch_s(s1, wk, wqkv_h + (size_t)D * D,      (size_t)D * D);
    split_hi_launch_s(s1, wv, wqkv_h + (size_t)2 * D * D,  (size_t)D * D);
    split_hi_launch_s(s1, wo, wo_h, (size_t)D * D);
    cudaEventRecord(ev_att, s1);
    split_launch_s(s1, w_gate, wg_h, wg_l, (size_t)FF * D);
    split_launch_s(s1, w_up,   wu_h, wu_l, (size_t)FF * D);
    split_launch_s(s1, w_down, wd_h, wd_l, (size_t)D * FF);
    cudaEventRecord(ev_ffn, s1);

    // ---- main stream: compute ----------------------------------------------
    k_rmsnorm_hi<<<S, 256>>>(x, w_rn1, h_h);
    cudaStreamWaitEvent(0, ev_att, 0);   // need wqkv/wo converts
    // merged q|k|v projection (1-pass), output [S, 6144]
    gemm_mma<0,1><<<gQKV, 256, SMEMB>>>(h_h, nullptr, wqkv_h, nullptr, qkvf, nullptr, nullptr, nullptr, S, 3 * D, D, 1.f);
    // rope (hi only) on q and k slices
    k_rope_hi<<<S, 256>>>(qkvf,         3 * D, cosb, sinb, q_h);
    k_rope_hi<<<S, 256>>>(qkvf + D,     3 * D, cosb, sinb, k_h);
    // v transpose (hi only) on v slice
    k_transpose_hi<<<dim3(D / 32, S / 32), 256>>>(qkvf + 2 * D, 3 * D, vt_h);
    // scores = q @ k^T / sqrt(D)   (1-pass), bf16 out straight into p_h
    gemm_mma<3,1><<<gSS, 256, SMEMB>>>(q_h, nullptr, k_h, nullptr, nullptr, nullptr, p_h, nullptr, S, S, D, inv_scale);
    // softmax in place on bf16
    k_softmax_bf<<<S, 256>>>(p_h);
    // attnv = P @ V  (1-pass), bf16 hi out
    gemm_mma<3,1><<<gDD, 256, SMEMB>>>(p_h, nullptr, vt_h, nullptr, nullptr, nullptr, av_h, nullptr, S, D, S, 1.f);
    // x1 = x + attnv @ wo^T  (1-pass)
    gemm_mma<0,1><<<gDD, 256, SMEMB>>>(av_h, nullptr, wo_h, nullptr, x1, x, nullptr, nullptr, S, D, D, 1.f);
    // h2 = rmsnorm(x1)*w_rn2 (full split — feeds undamped FFN)
    k_rmsnorm_split<<<S, 256>>>(x1, w_rn2, h2_h, h2_l);
    cudaStreamWaitEvent(0, ev_ffn, 0);   // join: FFN weight converts done
    // gate (3-pass, fp32 out)
    gemm_mma<0,3><<<gFFd, 256, SMEMB>>>(h2_h, h2_l, wg_h, wg_l, gf, nullptr, nullptr, nullptr, S, FF, D, 1.f);
    // up (3-pass) with fused SwiGLU epilogue
    gemm_mma<2,3><<<gFFd, 256, SMEMB>>>(h2_h, h2_l, wu_h, wu_l, nullptr, gf, act_h, act_l, S, FF, D, 1.f);
    // out = x1 + act @ w_down^T  (3-pass)
    gemm_mma<0,3><<<gDD, 256, SMEMB>>>(act_h, act_l, wd_h, wd_l, out, x1, nullptr, nullptr, S, D, FF, 1.f);
}